// round 7
// baseline (speedup 1.0000x reference)
#include <cuda_runtime.h>
#include <cuda_bf16.h>
#include <mma.h>

using namespace nvcuda;

// ---------------------------------------------------------------------------
// GraphEncoder: tf32 TC GEMMs (128-thread CTAs, 2 CTA/SM) + flash attention.
// Shapes: B=16, S=1024 (segments 512/256/256), H=256, heads=4 (Dh=64), F=400.
// ---------------------------------------------------------------------------

#define NB 16
#define SEQ 1024
#define HID 256
#define NHEADS 4
#define DH 64
#define FFP 512
#define TOKENS (NB * SEQ)

// -------------------- scratch (device globals; no allocation) --------------
__device__ float g_t[TOKENS * HID];
__device__ float g_x[TOKENS * HID];
__device__ float g_x1[TOKENS * HID];
__device__ float g_qkv[TOKENS * 3 * HID];
__device__ float g_ctx[TOKENS * HID];
__device__ float g_ff[TOKENS * FFP];
__device__ float g_mean[NB * 3 * HID];
__device__ float g_w1p[HID * FFP];
__device__ float g_b1p[FFP];
__device__ float g_w2p[FFP * HID];

__device__ __forceinline__ unsigned sptr(const void* p) {
    return (unsigned)__cvta_generic_to_shared(p);
}
#define CPA16(dst, src) asm volatile("cp.async.ca.shared.global [%0], [%1], 16;" :: "r"(dst), "l"(src))
#define CPA_COMMIT()    asm volatile("cp.async.commit_group;")
#define CPA_WAIT1()     asm volatile("cp.async.wait_group 1;")

// -------------------- generic tf32 GEMM (128x128 CTA, 128 thr) -------------
// C = A@B + bias (relu?), optional row-gather on A via aidx.
// M % 128 == 0, N % 128 == 0, K % 16 == 0.
#define BM 128
#define BN 128
#define BK 16
#define APAD 20
#define BPAD 132
#define AS_STAGE (BM * APAD)                 // 2560 floats
#define BS_STAGE (BK * BPAD)                 // 2112 floats
#define STAGES 3
#define BIAS_OFF (STAGES * (AS_STAGE + BS_STAGE))        // 14016
#define GEMM_SMEM_BYTES ((BIAS_OFF + 16 * BPAD) * 4)     // ~64.5 KB

__global__ void __launch_bounds__(128, 2) gemm_tc(
    const float* __restrict__ A, const float* __restrict__ Bm,
    const float* __restrict__ bias, float* __restrict__ C,
    int K, int lda, int ldb, int ldc,
    long sAb, long sBb, long sCb, int relu, const int* __restrict__ aidx)
{
    extern __shared__ float sm[];

    const int z = blockIdx.z;
    A  += (long)z * sAb;
    Bm += (long)z * sBb;
    C  += (long)z * sCb;

    const int tid = threadIdx.x;
    const int w = tid >> 5;
    const int wm = w & 1, wn = w >> 1;          // 2 x 2 warps, 64x64 tiles
    const int rowTile = blockIdx.y * BM;
    const int colTile = blockIdx.x * BN;

    auto loadA = [&](int kt, int s) {
        float* sa = sm + s * AS_STAGE;
        if (aidx) {
#pragma unroll
            for (int i = 0; i < 4; i++) {
                int idx = tid + i * 128;         // 512 f4: 128 rows x 4
                int r = idx >> 2, c4 = (idx & 3) * 4;
                long row = aidx[rowTile + r];
                CPA16(sptr(sa + r * APAD + c4), A + row * lda + kt * BK + c4);
            }
        } else {
            const float* Ag = A + (long)rowTile * lda + kt * BK;
#pragma unroll
            for (int i = 0; i < 4; i++) {
                int idx = tid + i * 128;
                int r = idx >> 2, c4 = (idx & 3) * 4;
                CPA16(sptr(sa + r * APAD + c4), Ag + (long)r * lda + c4);
            }
        }
    };
    auto loadB = [&](int kt, int s) {
        const float* Bg = Bm + (long)(kt * BK) * ldb + colTile;
        float* sb = sm + STAGES * AS_STAGE + s * BS_STAGE;
#pragma unroll
        for (int i = 0; i < 4; i++) {
            int idx = tid + i * 128;             // 512 f4: 16 rows x 32
            int r = idx >> 5, c4 = (idx & 31) * 4;
            CPA16(sptr(sb + r * BPAD + c4), Bg + (long)r * ldb + c4);
        }
    };

    float* biasm = sm + BIAS_OFF;
    if (bias) {
        for (int i = tid; i < 16 * 128; i += 128) {
            int r = i >> 7, c = i & 127;
            biasm[r * BPAD + c] = bias[colTile + c];
        }
    }

    loadA(0, 0); loadB(0, 0); CPA_COMMIT();
    loadA(1, 1); loadB(1, 1); CPA_COMMIT();
    __syncthreads();

    wmma::fragment<wmma::accumulator, 16, 16, 8, float> acc[4][4];
    if (bias) {
#pragma unroll
        for (int ni = 0; ni < 4; ni++) {
            wmma::load_matrix_sync(acc[0][ni], biasm + wn * 64 + ni * 16, BPAD,
                                   wmma::mem_row_major);
#pragma unroll
            for (int mi = 1; mi < 4; mi++) acc[mi][ni] = acc[0][ni];
        }
    } else {
#pragma unroll
        for (int mi = 0; mi < 4; mi++)
#pragma unroll
            for (int ni = 0; ni < 4; ni++) wmma::fill_fragment(acc[mi][ni], 0.f);
    }

    const int nk = K / BK;
    for (int kt = 0; kt < nk; kt++) {
        CPA_WAIT1();
        __syncthreads();
        if (kt + 2 < nk) { int s = (kt + 2) % STAGES; loadA(kt + 2, s); loadB(kt + 2, s); CPA_COMMIT(); }

        const float* sa = sm + (kt % STAGES) * AS_STAGE;
        const float* sb = sm + STAGES * AS_STAGE + (kt % STAGES) * BS_STAGE;

#pragma unroll
        for (int ks = 0; ks < 2; ks++) {
            wmma::fragment<wmma::matrix_a, 16, 16, 8, wmma::precision::tf32, wmma::row_major> af[4];
#pragma unroll
            for (int mi = 0; mi < 4; mi++)
                wmma::load_matrix_sync(af[mi], sa + (wm * 64 + mi * 16) * APAD + ks * 8, APAD);
            wmma::fragment<wmma::matrix_b, 16, 16, 8, wmma::precision::tf32, wmma::row_major> bf[4];
#pragma unroll
            for (int ni = 0; ni < 4; ni++)
                wmma::load_matrix_sync(bf[ni], sb + (ks * 8) * BPAD + wn * 64 + ni * 16, BPAD);
#pragma unroll
            for (int mi = 0; mi < 4; mi++)
#pragma unroll
                for (int ni = 0; ni < 4; ni++)
                    wmma::mma_sync(acc[mi][ni], af[mi], bf[ni], acc[mi][ni]);
        }
        __syncthreads();
    }

#pragma unroll
    for (int mi = 0; mi < 4; mi++)
#pragma unroll
        for (int ni = 0; ni < 4; ni++) {
            if (relu)
#pragma unroll
                for (int e = 0; e < acc[mi][ni].num_elements; e++)
                    acc[mi][ni].x[e] = fmaxf(acc[mi][ni].x[e], 0.f);
            wmma::store_matrix_sync(
                C + (long)(rowTile + wm * 64 + mi * 16) * ldc + colTile + wn * 64 + ni * 16,
                acc[mi][ni], ldc, wmma::mem_row_major);
        }
}

// -------------------- GEMM + residual + LayerNorm fused --------------------
// out = LN(res + A@B + bias)   with N == 256 (one CTA per 128-row strip).
#define LBM 128
#define LAPAD 20
#define LBPAD 260
#define LAS_STAGE (LBM * LAPAD)
#define LBS_STAGE (BK * LBPAD)
#define LEPI_OFF (STAGES * (LAS_STAGE + LBS_STAGE))
#define LN_SMEM_BYTES ((LEPI_OFF + LBM * LBPAD + 2 * LBM) * 4)

__global__ void __launch_bounds__(256, 1) gemm_ln(
    const float* __restrict__ A, const float* __restrict__ Bm,
    const float* __restrict__ bias, const float* __restrict__ res,
    const float* __restrict__ lng, const float* __restrict__ lnb,
    float* __restrict__ out, int K, int lda)
{
    extern __shared__ float sm[];
    float* epi = sm + LEPI_OFF;
    float* smu = epi + LBM * LBPAD;
    float* srs = smu + LBM;

    const int tid = threadIdx.x;
    const int w = tid >> 5;
    const int wm = w & 1, wn = w >> 1;          // 2 x 4 warps, 64x64 tiles
    const int rowTile = blockIdx.x * LBM;

    auto loadA = [&](int kt, int s) {
        const float* Ag = A + (long)rowTile * lda + kt * BK;
        float* sa = sm + s * LAS_STAGE;
#pragma unroll
        for (int i = 0; i < 2; i++) {
            int idx = tid + i * 256;
            int r = idx >> 2, c4 = (idx & 3) * 4;
            CPA16(sptr(sa + r * LAPAD + c4), Ag + (long)r * lda + c4);
        }
    };
    auto loadB = [&](int kt, int s) {
        const float* Bg = Bm + (long)(kt * BK) * 256;
        float* sb = sm + STAGES * LAS_STAGE + s * LBS_STAGE;
#pragma unroll
        for (int i = 0; i < 4; i++) {
            int idx = tid + i * 256;
            int r = idx >> 6, c4 = (idx & 63) * 4;
            CPA16(sptr(sb + r * LBPAD + c4), Bg + (long)r * 256 + c4);
        }
    };

    loadA(0, 0); loadB(0, 0); CPA_COMMIT();
    loadA(1, 1); loadB(1, 1); CPA_COMMIT();

    wmma::fragment<wmma::accumulator, 16, 16, 8, float> acc[4][4];
#pragma unroll
    for (int mi = 0; mi < 4; mi++)
#pragma unroll
        for (int ni = 0; ni < 4; ni++) wmma::fill_fragment(acc[mi][ni], 0.f);

    const int nk = K / BK;
    for (int kt = 0; kt < nk; kt++) {
        CPA_WAIT1();
        __syncthreads();
        if (kt + 2 < nk) { int s = (kt + 2) % STAGES; loadA(kt + 2, s); loadB(kt + 2, s); CPA_COMMIT(); }

        const float* sa = sm + (kt % STAGES) * LAS_STAGE;
        const float* sb = sm + STAGES * LAS_STAGE + (kt % STAGES) * LBS_STAGE;

#pragma unroll
        for (int ks = 0; ks < 2; ks++) {
            wmma::fragment<wmma::matrix_a, 16, 16, 8, wmma::precision::tf32, wmma::row_major> af[4];
#pragma unroll
            for (int mi = 0; mi < 4; mi++)
                wmma::load_matrix_sync(af[mi], sa + (wm * 64 + mi * 16) * LAPAD + ks * 8, LAPAD);
            wmma::fragment<wmma::matrix_b, 16, 16, 8, wmma::precision::tf32, wmma::row_major> bf[4];
#pragma unroll
            for (int ni = 0; ni < 4; ni++)
                wmma::load_matrix_sync(bf[ni], sb + (ks * 8) * LBPAD + wn * 64 + ni * 16, LBPAD);
#pragma unroll
            for (int mi = 0; mi < 4; mi++)
#pragma unroll
                for (int ni = 0; ni < 4; ni++)
                    wmma::mma_sync(acc[mi][ni], af[mi], bf[ni], acc[mi][ni]);
        }
    }
    __syncthreads();

#pragma unroll
    for (int mi = 0; mi < 4; mi++)
#pragma unroll
        for (int ni = 0; ni < 4; ni++)
            wmma::store_matrix_sync(epi + (wm * 64 + mi * 16) * LBPAD + wn * 64 + ni * 16,
                                    acc[mi][ni], LBPAD, wmma::mem_row_major);
    __syncthreads();

#pragma unroll 8
    for (int i = 0; i < 128; i++) {
        int idx = tid + i * 256;
        int r = idx >> 8, c = idx & 255;
        epi[r * LBPAD + c] += bias[c] + res[(long)(rowTile + r) * HID + c];
    }
    __syncthreads();

    {
        const int r = tid >> 1, hf = tid & 1;
        const float* row = epi + r * LBPAD + hf * 128;
        float s = 0.f, s2 = 0.f;
#pragma unroll 8
        for (int c = 0; c < 128; c++) { float v = row[c]; s += v; s2 += v * v; }
        s  += __shfl_xor_sync(0xffffffffu, s, 1);
        s2 += __shfl_xor_sync(0xffffffffu, s2, 1);
        if (hf == 0) {
            float mu = s * (1.f / 256.f);
            float var = s2 * (1.f / 256.f) - mu * mu;
            smu[r] = mu;
            srs[r] = rsqrtf(var + 1e-5f);
        }
    }
    __syncthreads();

#pragma unroll 8
    for (int i = 0; i < 128; i++) {
        int idx = tid + i * 256;
        int r = idx >> 8, c = idx & 255;
        float v = (epi[r * LBPAD + c] - smu[r]) * srs[r] * lng[c] + lnb[c];
        out[(long)(rowTile + r) * HID + c] = v;
    }
}

// -------------------- fused flash attention --------------------------------
#define QLD 68
#define SLD 132
#define FS_Q 0
#define FS_K 8704
#define FS_V 17408
#define FS_O 26112
#define FS_S 34816
#define FS_AL 51712
#define FS_M 51840
#define FS_L 51968
#define FLASH_SMEM_BYTES ((51968 + 128) * 4)

__global__ void __launch_bounds__(256) flash_k(
    const float* __restrict__ qkv, float* __restrict__ ctx, int segOff, int L)
{
    extern __shared__ float sm[];
    float* sQ = sm + FS_Q;
    float* sK = sm + FS_K;
    float* sV = sm + FS_V;
    float* sO = sm + FS_O;
    float* sS = sm + FS_S;
    float* al = sm + FS_AL;
    float* mrow = sm + FS_M;
    float* lrow = sm + FS_L;

    const int bh = blockIdx.y;
    const int b = bh >> 2, h = bh & 3;
    const int qt = blockIdx.x;
    const int tid = threadIdx.x;
    const int w = tid >> 5;
    const int wm = w & 3, wn = w >> 2;

    const float* base = qkv + ((long)b * SEQ + segOff) * 768 + h * 64;
    const float* Qg = base + (long)qt * 128 * 768;

#pragma unroll
    for (int i = 0; i < 8; i++) {
        int idx = tid + i * 256;
        int r = idx >> 4, c4 = (idx & 15) * 4;
        *(float4*)(sQ + r * QLD + c4) = *(const float4*)(Qg + (long)r * 768 + c4);
        *(float4*)(sO + r * QLD + c4) = make_float4(0.f, 0.f, 0.f, 0.f);
    }
    if (tid < 128) { mrow[tid] = -1e30f; lrow[tid] = 0.f; }
    __syncthreads();

    const int nt = L >> 7;
    for (int t = 0; t < nt; t++) {
        const float* Kg = base + 256 + (long)t * 128 * 768;
        const float* Vg = base + 512 + (long)t * 128 * 768;
#pragma unroll
        for (int i = 0; i < 8; i++) {
            int idx = tid + i * 256;
            int r = idx >> 4, c4 = (idx & 15) * 4;
            *(float4*)(sK + r * QLD + c4) = *(const float4*)(Kg + (long)r * 768 + c4);
            *(float4*)(sV + r * QLD + c4) = *(const float4*)(Vg + (long)r * 768 + c4);
        }
        __syncthreads();

        {
            wmma::fragment<wmma::accumulator, 16, 16, 8, float> sacc[2][4];
#pragma unroll
            for (int mi = 0; mi < 2; mi++)
#pragma unroll
                for (int ni = 0; ni < 4; ni++) wmma::fill_fragment(sacc[mi][ni], 0.f);
#pragma unroll
            for (int k = 0; k < DH; k += 8) {
                wmma::fragment<wmma::matrix_a, 16, 16, 8, wmma::precision::tf32, wmma::row_major> af[2];
#pragma unroll
                for (int mi = 0; mi < 2; mi++)
                    wmma::load_matrix_sync(af[mi], sQ + (wm * 32 + mi * 16) * QLD + k, QLD);
                wmma::fragment<wmma::matrix_b, 16, 16, 8, wmma::precision::tf32, wmma::col_major> bf[4];
#pragma unroll
                for (int ni = 0; ni < 4; ni++)
                    wmma::load_matrix_sync(bf[ni], sK + (wn * 64 + ni * 16) * QLD + k, QLD);
#pragma unroll
                for (int mi = 0; mi < 2; mi++)
#pragma unroll
                    for (int ni = 0; ni < 4; ni++)
                        wmma::mma_sync(sacc[mi][ni], af[mi], bf[ni], sacc[mi][ni]);
            }
#pragma unroll
            for (int mi = 0; mi < 2; mi++)
#pragma unroll
                for (int ni = 0; ni < 4; ni++)
                    wmma::store_matrix_sync(sS + (wm * 32 + mi * 16) * SLD + wn * 64 + ni * 16,
                                            sacc[mi][ni], SLD, wmma::mem_row_major);
        }
        __syncthreads();

        {
            const int r = tid >> 1, hf = tid & 1;
            float* row = sS + r * SLD + hf * 64;
            float mx = -1e30f;
#pragma unroll 8
            for (int c = 0; c < 64; c++) mx = fmaxf(mx, row[c]);
            mx = fmaxf(mx, __shfl_xor_sync(0xffffffffu, mx, 1));
            mx *= 0.125f;
            float m_old = mrow[r];
            float m_new = fmaxf(m_old, mx);
            float a = __expf(m_old - m_new);
            float sum = 0.f;
#pragma unroll 8
            for (int c = 0; c < 64; c++) {
                float p = __expf(row[c] * 0.125f - m_new);
                row[c] = p;
                sum += p;
            }
            sum += __shfl_xor_sync(0xffffffffu, sum, 1);
            if (hf == 0) {
                mrow[r] = m_new;
                lrow[r] = lrow[r] * a + sum;
                al[r] = a;
            }
        }
        __syncthreads();

        {
            wmma::fragment<wmma::accumulator, 16, 16, 8, float> oacc[2][2];
#pragma unroll
            for (int mi = 0; mi < 2; mi++)
#pragma unroll
                for (int ni = 0; ni < 2; ni++) wmma::fill_fragment(oacc[mi][ni], 0.f);
#pragma unroll
            for (int k = 0; k < 128; k += 8) {
                wmma::fragment<wmma::matrix_a, 16, 16, 8, wmma::precision::tf32, wmma::row_major> af[2];
#pragma unroll
                for (int mi = 0; mi < 2; mi++)
                    wmma::load_matrix_sync(af[mi], sS + (wm * 32 + mi * 16) * SLD + k, SLD);
                wmma::fragment<wmma::matrix_b, 16, 16, 8, wmma::precision::tf32, wmma::row_major> bf[2];
#pragma unroll
                for (int ni = 0; ni < 2; ni++)
                    wmma::load_matrix_sync(bf[ni], sV + k * QLD + wn * 32 + ni * 16, QLD);
#pragma unroll
                for (int mi = 0; mi < 2; mi++)
#pragma unroll
                    for (int ni = 0; ni < 2; ni++)
                        wmma::mma_sync(oacc[mi][ni], af[mi], bf[ni], oacc[mi][ni]);
            }
            __syncthreads();
#pragma unroll
            for (int mi = 0; mi < 2; mi++)
#pragma unroll
                for (int ni = 0; ni < 2; ni++)
                    wmma::store_matrix_sync(sS + (wm * 32 + mi * 16) * SLD + wn * 32 + ni * 16,
                                            oacc[mi][ni], SLD, wmma::mem_row_major);
        }
        __syncthreads();

        {
            const int r = tid >> 1, hf = tid & 1;
            const float a = al[r];
            float* orow = sO + r * QLD + hf * 32;
            const float* prow = sS + r * SLD + hf * 32;
#pragma unroll 8
            for (int c = 0; c < 32; c++) orow[c] = orow[c] * a + prow[c];
        }
        __syncthreads();
    }

    float* out = ctx + ((long)b * SEQ + segOff + (long)qt * 128) * HID + h * 64;
    {
        const int r = tid >> 1, hf = tid & 1;
        const float inv = 1.f / lrow[r];
#pragma unroll
        for (int c4 = 0; c4 < 32; c4 += 4) {
            int c = hf * 32 + c4;
            float4 v = *(float4*)(sO + r * QLD + c);
            v.x *= inv; v.y *= inv; v.z *= inv; v.w *= inv;
            *(float4*)(out + (long)r * HID + c) = v;
        }
    }
}

// -------------------- small kernels -----------------------------------------
__global__ void pad_w1_k(const float* __restrict__ w, float* __restrict__ o)
{
    int i = blockIdx.x * 256 + threadIdx.x;
    int r = i >> 9, c = i & 511;
    o[i] = (c < 400) ? w[r * 400 + c] : 0.f;
}
__global__ void pad_b1_k(const float* __restrict__ b, float* __restrict__ o)
{
    int c = threadIdx.x + blockIdx.x * 256;
    o[c] = (c < 400) ? b[c] : 0.f;
}
__global__ void pad_w2_k(const float* __restrict__ w, float* __restrict__ o)
{
    int i = blockIdx.x * 256 + threadIdx.x;
    int r = i >> 8, c = i & 255;
    o[i] = (r < 400) ? w[r * 256 + c] : 0.f;
}

__global__ void zero_mean_k(float* __restrict__ m)
{
    m[blockIdx.x * 256 + threadIdx.x] = 0.f;
}

__global__ void mean_part_k(const float* __restrict__ x, float* __restrict__ mout)
{
    int seg = blockIdx.x, part = blockIdx.y;
    int b = seg / 3, sgi = seg % 3;
    int off = (sgi == 0) ? 0 : (sgi == 1 ? 512 : 768);
    int L   = (sgi == 0) ? 512 : 256;
    int rows = L >> 3;
    int t = threadIdx.x;
    const float* p = x + ((long)b * SEQ + off + part * rows) * HID + t;
    float s = 0.f;
    for (int i = 0; i < rows; i++) s += p[(long)i * HID];
    atomicAdd(&mout[(long)seg * HID + t], s);
}

__global__ void final_k(const float* __restrict__ mean, const float* __restrict__ W,
                        const float* __restrict__ bias, float* __restrict__ out)
{
    int b = blockIdx.x, n = threadIdx.x;
    __shared__ float comb[HID];
    const float* mp = mean + (long)b * 3 * HID;
    comb[n] = mp[n] * (1.f / 512.f) - mp[HID + n] * (1.f / 256.f)
            + mp[2 * HID + n] * (1.f / 256.f);
    __syncthreads();
    float s = bias[n];
#pragma unroll 8
    for (int k = 0; k < HID; k++) s += comb[k] * W[k * HID + n];
    out[(long)b * HID + n] = fmaxf(s, 0.f);
}

// ---------------------------------------------------------------------------
static void launch_gemm(const float* A, const float* B, const float* bias, float* C,
                        int M, int N, int K, int lda, int ldb, int ldc,
                        long sAb, long sBb, long sCb, int batches, int relu,
                        const int* aidx = nullptr)
{
    dim3 grid(N / BN, M / BM, batches);
    gemm_tc<<<grid, 128, GEMM_SMEM_BYTES>>>(A, B, bias, C, K, lda, ldb, ldc,
                                            sAb, sBb, sCb, relu, aidx);
}

extern "C" void kernel_launch(void* const* d_in, const int* in_sizes, int n_in,
                              void* d_out, int out_size)
{
    const int*   hyper = (const int*)  d_in[0];
    const float* HT    = (const float*)d_in[1];
    const float* emb   = (const float*)d_in[2];
    const float* Wg1   = (const float*)d_in[3];
    const float* bg1   = (const float*)d_in[4];
    const float* Wg2   = (const float*)d_in[5];
    const float* bg2   = (const float*)d_in[6];
    const float* Wqkv  = (const float*)d_in[7];
    const float* bqkv  = (const float*)d_in[8];
    const float* Wo    = (const float*)d_in[9];
    const float* bo    = (const float*)d_in[10];
    const float* ln1g  = (const float*)d_in[11];
    const float* ln1b  = (const float*)d_in[12];
    const float* Wff1  = (const float*)d_in[13];
    const float* bff1  = (const float*)d_in[14];
    const float* Wff2  = (const float*)d_in[15];
    const float* bff2  = (const float*)d_in[16];
    const float* ln2g  = (const float*)d_in[17];
    const float* ln2b  = (const float*)d_in[18];
    const float* fc1W  = (const float*)d_in[19];
    const float* fc1b  = (const float*)d_in[20];

    float *t, *x, *x1, *qkv, *ctx, *ff, *mean, *w1p, *b1p, *w2p;
    cudaGetSymbolAddress((void**)&t,    g_t);
    cudaGetSymbolAddress((void**)&x,    g_x);
    cudaGetSymbolAddress((void**)&x1,   g_x1);
    cudaGetSymbolAddress((void**)&qkv,  g_qkv);
    cudaGetSymbolAddress((void**)&ctx,  g_ctx);
    cudaGetSymbolAddress((void**)&ff,   g_ff);
    cudaGetSymbolAddress((void**)&mean, g_mean);
    cudaGetSymbolAddress((void**)&w1p,  g_w1p);
    cudaGetSymbolAddress((void**)&b1p,  g_b1p);
    cudaGetSymbolAddress((void**)&w2p,  g_w2p);

    cudaFuncSetAttribute(flash_k, cudaFuncAttributeMaxDynamicSharedMemorySize,
                         FLASH_SMEM_BYTES);
    cudaFuncSetAttribute(gemm_tc, cudaFuncAttributeMaxDynamicSharedMemorySize,
                         GEMM_SMEM_BYTES);
    cudaFuncSetAttribute(gemm_ln, cudaFuncAttributeMaxDynamicSharedMemorySize,
                         LN_SMEM_BYTES);

    // 0. pad FF weights
    pad_w1_k<<<HID * FFP / 256, 256>>>(Wff1, w1p);
    pad_b1_k<<<2, 256>>>(bff1, b1p);
    pad_w2_k<<<FFP * HID / 256, 256>>>(Wff2, w2p);

    // 1. t = emb[hyper] @ Wg1   (gather fused)
    launch_gemm(emb, Wg1, nullptr, t, TOKENS, HID, HID, HID, HID, HID,
                0, 0, 0, 1, 0, hyper);

    // 2. x = batched HT @ t + bg1
    launch_gemm(HT, t, bg1, x, SEQ, HID, SEQ, SEQ, HID, HID,
                (long)SEQ * SEQ, (long)SEQ * HID, (long)SEQ * HID, NB, 0);

    // 3. t = x @ Wg2
    launch_gemm(x, Wg2, nullptr, t, TOKENS, HID, HID, HID, HID, HID, 0, 0, 0, 1, 0);

    // 4. x = batched HT @ t + bg2
    launch_gemm(HT, t, bg2, x, SEQ, HID, SEQ, SEQ, HID, HID,
                (long)SEQ * SEQ, (long)SEQ * HID, (long)SEQ * HID, NB, 0);

    // 5. qkv = x @ Wqkv + bqkv
    launch_gemm(x, Wqkv, bqkv, qkv, TOKENS, 3 * HID, HID, HID, 3 * HID, 3 * HID,
                0, 0, 0, 1, 0);

    // 6. fused flash attention per segment
    flash_k<<<dim3(4, NB * NHEADS), 256, FLASH_SMEM_BYTES>>>(qkv, ctx, 0, 512);
    flash_k<<<dim3(2, NB * NHEADS), 256, FLASH_SMEM_BYTES>>>(qkv, ctx, 512, 256);
    flash_k<<<dim3(2, NB * NHEADS), 256, FLASH_SMEM_BYTES>>>(qkv, ctx, 768, 256);

    // 7. x1 = LN1(x + ctx @ Wo + bo)
    gemm_ln<<<TOKENS / LBM, 256, LN_SMEM_BYTES>>>(ctx, Wo, bo, x, ln1g, ln1b,
                                                  x1, HID, HID);

    // 8. ff = relu(x1 @ w1p + b1p)
    launch_gemm(x1, w1p, b1p, ff, TOKENS, FFP, HID, HID, FFP, FFP, 0, 0, 0, 1, 1);

    // 9. x = LN2(x1 + ff @ w2p + bff2)
    gemm_ln<<<TOKENS / LBM, 256, LN_SMEM_BYTES>>>(ff, w2p, bff2, x1, ln2g, ln2b,
                                                  x, FFP, FFP);

    // 10. segment means (two-stage)
    zero_mean_k<<<NB * 3, 256>>>(mean);
    mean_part_k<<<dim3(NB * 3, 8), 256>>>(x, mean);

    // 11. out = relu((p - n + f) @ fc1W + fc1b)
    final_k<<<NB, 256>>>(mean, fc1W, fc1b, (float*)d_out);
}

// round 8
// speedup vs baseline: 1.0411x; 1.0411x over previous
#include <cuda_runtime.h>
#include <cuda_bf16.h>
#include <mma.h>

using namespace nvcuda;

// ---------------------------------------------------------------------------
// GraphEncoder: tf32 TC GEMMs + register-accumulator flash attention.
// Shapes: B=16, S=1024 (segments 512/256/256), H=256, heads=4 (Dh=64), F=400.
// ---------------------------------------------------------------------------

#define NB 16
#define SEQ 1024
#define HID 256
#define NHEADS 4
#define DH 64
#define FFP 512
#define TOKENS (NB * SEQ)

// -------------------- scratch (device globals; no allocation) --------------
__device__ float g_t[TOKENS * HID];
__device__ float g_x[TOKENS * HID];
__device__ float g_x1[TOKENS * HID];
__device__ float g_qkv[TOKENS * 3 * HID];
__device__ float g_ctx[TOKENS * HID];
__device__ float g_ff[TOKENS * FFP];
__device__ float g_mean[NB * 3 * HID];
__device__ float g_w1p[HID * FFP];
__device__ float g_b1p[FFP];
__device__ float g_w2p[FFP * HID];
__device__ int   g_rowtab[256];          // wmma acc element -> row map

__device__ __forceinline__ unsigned sptr(const void* p) {
    return (unsigned)__cvta_generic_to_shared(p);
}
#define CPA16(dst, src) asm volatile("cp.async.ca.shared.global [%0], [%1], 16;" :: "r"(dst), "l"(src))
#define CPA_COMMIT()    asm volatile("cp.async.commit_group;")
#define CPA_WAIT0()     asm volatile("cp.async.wait_group 0;")
#define CPA_WAIT1()     asm volatile("cp.async.wait_group 1;")

// -------------------- probe: measure wmma fp32 acc element->row map --------
__global__ void probe_k(int* __restrict__ rowtab)
{
    __shared__ float pat[16 * 16];
    int lane = threadIdx.x;
    for (int i = lane; i < 256; i += 32) pat[i] = (float)(i >> 4);  // value = row
    __syncwarp();
    wmma::fragment<wmma::accumulator, 16, 16, 8, float> f;
    wmma::load_matrix_sync(f, pat, 16, wmma::mem_row_major);
#pragma unroll
    for (int e = 0; e < f.num_elements && e < 8; e++)
        rowtab[lane * 8 + e] = (int)f.x[e];
}

// -------------------- generic tf32 GEMM (128x128 CTA, 128 thr) -------------
#define BM 128
#define BN 128
#define BK 16
#define APAD 20
#define BPAD 132
#define AS_STAGE (BM * APAD)
#define BS_STAGE (BK * BPAD)
#define STAGES 3
#define BIAS_OFF (STAGES * (AS_STAGE + BS_STAGE))
#define GEMM_SMEM_BYTES ((BIAS_OFF + 16 * BPAD) * 4)

__global__ void __launch_bounds__(128, 2) gemm_tc(
    const float* __restrict__ A, const float* __restrict__ Bm,
    const float* __restrict__ bias, float* __restrict__ C,
    int K, int lda, int ldb, int ldc,
    long sAb, long sBb, long sCb, int relu, const int* __restrict__ aidx)
{
    extern __shared__ float sm[];

    const int z = blockIdx.z;
    A  += (long)z * sAb;
    Bm += (long)z * sBb;
    C  += (long)z * sCb;

    const int tid = threadIdx.x;
    const int w = tid >> 5;
    const int wm = w & 1, wn = w >> 1;
    const int rowTile = blockIdx.y * BM;
    const int colTile = blockIdx.x * BN;

    auto loadA = [&](int kt, int s) {
        float* sa = sm + s * AS_STAGE;
        if (aidx) {
#pragma unroll
            for (int i = 0; i < 4; i++) {
                int idx = tid + i * 128;
                int r = idx >> 2, c4 = (idx & 3) * 4;
                long row = aidx[rowTile + r];
                CPA16(sptr(sa + r * APAD + c4), A + row * lda + kt * BK + c4);
            }
        } else {
            const float* Ag = A + (long)rowTile * lda + kt * BK;
#pragma unroll
            for (int i = 0; i < 4; i++) {
                int idx = tid + i * 128;
                int r = idx >> 2, c4 = (idx & 3) * 4;
                CPA16(sptr(sa + r * APAD + c4), Ag + (long)r * lda + c4);
            }
        }
    };
    auto loadB = [&](int kt, int s) {
        const float* Bg = Bm + (long)(kt * BK) * ldb + colTile;
        float* sb = sm + STAGES * AS_STAGE + s * BS_STAGE;
#pragma unroll
        for (int i = 0; i < 4; i++) {
            int idx = tid + i * 128;
            int r = idx >> 5, c4 = (idx & 31) * 4;
            CPA16(sptr(sb + r * BPAD + c4), Bg + (long)r * ldb + c4);
        }
    };

    float* biasm = sm + BIAS_OFF;
    if (bias) {
        for (int i = tid; i < 16 * 128; i += 128) {
            int r = i >> 7, c = i & 127;
            biasm[r * BPAD + c] = bias[colTile + c];
        }
    }

    loadA(0, 0); loadB(0, 0); CPA_COMMIT();
    loadA(1, 1); loadB(1, 1); CPA_COMMIT();
    __syncthreads();

    wmma::fragment<wmma::accumulator, 16, 16, 8, float> acc[4][4];
    if (bias) {
#pragma unroll
        for (int ni = 0; ni < 4; ni++) {
            wmma::load_matrix_sync(acc[0][ni], biasm + wn * 64 + ni * 16, BPAD,
                                   wmma::mem_row_major);
#pragma unroll
            for (int mi = 1; mi < 4; mi++) acc[mi][ni] = acc[0][ni];
        }
    } else {
#pragma unroll
        for (int mi = 0; mi < 4; mi++)
#pragma unroll
            for (int ni = 0; ni < 4; ni++) wmma::fill_fragment(acc[mi][ni], 0.f);
    }

    const int nk = K / BK;
    for (int kt = 0; kt < nk; kt++) {
        CPA_WAIT1();
        __syncthreads();
        if (kt + 2 < nk) { int s = (kt + 2) % STAGES; loadA(kt + 2, s); loadB(kt + 2, s); CPA_COMMIT(); }

        const float* sa = sm + (kt % STAGES) * AS_STAGE;
        const float* sb = sm + STAGES * AS_STAGE + (kt % STAGES) * BS_STAGE;

#pragma unroll
        for (int ks = 0; ks < 2; ks++) {
            wmma::fragment<wmma::matrix_a, 16, 16, 8, wmma::precision::tf32, wmma::row_major> af[4];
#pragma unroll
            for (int mi = 0; mi < 4; mi++)
                wmma::load_matrix_sync(af[mi], sa + (wm * 64 + mi * 16) * APAD + ks * 8, APAD);
            wmma::fragment<wmma::matrix_b, 16, 16, 8, wmma::precision::tf32, wmma::row_major> bf[4];
#pragma unroll
            for (int ni = 0; ni < 4; ni++)
                wmma::load_matrix_sync(bf[ni], sb + (ks * 8) * BPAD + wn * 64 + ni * 16, BPAD);
#pragma unroll
            for (int mi = 0; mi < 4; mi++)
#pragma unroll
                for (int ni = 0; ni < 4; ni++)
                    wmma::mma_sync(acc[mi][ni], af[mi], bf[ni], acc[mi][ni]);
        }
    }

#pragma unroll
    for (int mi = 0; mi < 4; mi++)
#pragma unroll
        for (int ni = 0; ni < 4; ni++) {
            if (relu)
#pragma unroll
                for (int e = 0; e < acc[mi][ni].num_elements; e++)
                    acc[mi][ni].x[e] = fmaxf(acc[mi][ni].x[e], 0.f);
            wmma::store_matrix_sync(
                C + (long)(rowTile + wm * 64 + mi * 16) * ldc + colTile + wn * 64 + ni * 16,
                acc[mi][ni], ldc, wmma::mem_row_major);
        }
}

// -------------------- GEMM + residual + LayerNorm fused --------------------
#define LBM 128
#define LAPAD 20
#define LBPAD 260
#define LAS_STAGE (LBM * LAPAD)
#define LBS_STAGE (BK * LBPAD)
#define LEPI_OFF (STAGES * (LAS_STAGE + LBS_STAGE))
#define LN_SMEM_BYTES ((LEPI_OFF + LBM * LBPAD + 2 * LBM) * 4)

__global__ void __launch_bounds__(256, 1) gemm_ln(
    const float* __restrict__ A, const float* __restrict__ Bm,
    const float* __restrict__ bias, const float* __restrict__ res,
    const float* __restrict__ lng, const float* __restrict__ lnb,
    float* __restrict__ out, int K, int lda)
{
    extern __shared__ float sm[];
    float* epi = sm + LEPI_OFF;
    float* smu = epi + LBM * LBPAD;
    float* srs = smu + LBM;

    const int tid = threadIdx.x;
    const int w = tid >> 5;
    const int wm = w & 1, wn = w >> 1;
    const int rowTile = blockIdx.x * LBM;

    auto loadA = [&](int kt, int s) {
        const float* Ag = A + (long)rowTile * lda + kt * BK;
        float* sa = sm + s * LAS_STAGE;
#pragma unroll
        for (int i = 0; i < 2; i++) {
            int idx = tid + i * 256;
            int r = idx >> 2, c4 = (idx & 3) * 4;
            CPA16(sptr(sa + r * LAPAD + c4), Ag + (long)r * lda + c4);
        }
    };
    auto loadB = [&](int kt, int s) {
        const float* Bg = Bm + (long)(kt * BK) * 256;
        float* sb = sm + STAGES * LAS_STAGE + s * LBS_STAGE;
#pragma unroll
        for (int i = 0; i < 4; i++) {
            int idx = tid + i * 256;
            int r = idx >> 6, c4 = (idx & 63) * 4;
            CPA16(sptr(sb + r * LBPAD + c4), Bg + (long)r * 256 + c4);
        }
    };

    loadA(0, 0); loadB(0, 0); CPA_COMMIT();
    loadA(1, 1); loadB(1, 1); CPA_COMMIT();

    wmma::fragment<wmma::accumulator, 16, 16, 8, float> acc[4][4];
#pragma unroll
    for (int mi = 0; mi < 4; mi++)
#pragma unroll
        for (int ni = 0; ni < 4; ni++) wmma::fill_fragment(acc[mi][ni], 0.f);

    const int nk = K / BK;
    for (int kt = 0; kt < nk; kt++) {
        CPA_WAIT1();
        __syncthreads();
        if (kt + 2 < nk) { int s = (kt + 2) % STAGES; loadA(kt + 2, s); loadB(kt + 2, s); CPA_COMMIT(); }

        const float* sa = sm + (kt % STAGES) * LAS_STAGE;
        const float* sb = sm + STAGES * LAS_STAGE + (kt % STAGES) * LBS_STAGE;

#pragma unroll
        for (int ks = 0; ks < 2; ks++) {
            wmma::fragment<wmma::matrix_a, 16, 16, 8, wmma::precision::tf32, wmma::row_major> af[4];
#pragma unroll
            for (int mi = 0; mi < 4; mi++)
                wmma::load_matrix_sync(af[mi], sa + (wm * 64 + mi * 16) * LAPAD + ks * 8, LAPAD);
            wmma::fragment<wmma::matrix_b, 16, 16, 8, wmma::precision::tf32, wmma::row_major> bf[4];
#pragma unroll
            for (int ni = 0; ni < 4; ni++)
                wmma::load_matrix_sync(bf[ni], sb + (ks * 8) * LBPAD + wn * 64 + ni * 16, LBPAD);
#pragma unroll
            for (int mi = 0; mi < 4; mi++)
#pragma unroll
                for (int ni = 0; ni < 4; ni++)
                    wmma::mma_sync(acc[mi][ni], af[mi], bf[ni], acc[mi][ni]);
        }
    }
    __syncthreads();

#pragma unroll
    for (int mi = 0; mi < 4; mi++)
#pragma unroll
        for (int ni = 0; ni < 4; ni++)
            wmma::store_matrix_sync(epi + (wm * 64 + mi * 16) * LBPAD + wn * 64 + ni * 16,
                                    acc[mi][ni], LBPAD, wmma::mem_row_major);
    __syncthreads();

#pragma unroll 8
    for (int i = 0; i < 128; i++) {
        int idx = tid + i * 256;
        int r = idx >> 8, c = idx & 255;
        epi[r * LBPAD + c] += bias[c] + res[(long)(rowTile + r) * HID + c];
    }
    __syncthreads();

    {
        const int r = tid >> 1, hf = tid & 1;
        const float* row = epi + r * LBPAD + hf * 128;
        float s = 0.f, s2 = 0.f;
#pragma unroll 8
        for (int c = 0; c < 128; c++) { float v = row[c]; s += v; s2 += v * v; }
        s  += __shfl_xor_sync(0xffffffffu, s, 1);
        s2 += __shfl_xor_sync(0xffffffffu, s2, 1);
        if (hf == 0) {
            float mu = s * (1.f / 256.f);
            float var = s2 * (1.f / 256.f) - mu * mu;
            smu[r] = mu;
            srs[r] = rsqrtf(var + 1e-5f);
        }
    }
    __syncthreads();

#pragma unroll 8
    for (int i = 0; i < 128; i++) {
        int idx = tid + i * 256;
        int r = idx >> 8, c = idx & 255;
        float v = (epi[r * LBPAD + c] - smu[r]) * srs[r] * lng[c] + lnb[c];
        out[(long)(rowTile + r) * HID + c] = v;
    }
}

// -------------------- flash attention v2 (O in registers) ------------------
#define QLD 68
#define SLD 132
#define FS_Q 0
#define FS_K 8704
#define FS_V 17408
#define FS_S 26112
#define FS_AL 43008
#define FS_M 43136
#define FS_L 43264
#define FLASH_SMEM_BYTES (43392 * 4)   // 173568 B

__global__ void __launch_bounds__(256) flash_k(
    const float* __restrict__ qkv, float* __restrict__ ctx,
    const int* __restrict__ rowtab)
{
    extern __shared__ float sm[];
    float* sQ = sm + FS_Q;
    float* sK = sm + FS_K;
    float* sV = sm + FS_V;
    float* sS = sm + FS_S;
    float* al = sm + FS_AL;
    float* mrow = sm + FS_M;
    float* lrow = sm + FS_L;

    // decode segment / q-tile from blockIdx.x (0..7)
    const int bx = blockIdx.x;
    int segOff, L, qt;
    if (bx < 4)      { segOff = 0;   L = 512; qt = bx; }
    else if (bx < 6) { segOff = 512; L = 256; qt = bx - 4; }
    else             { segOff = 768; L = 256; qt = bx - 6; }

    const int bh = blockIdx.y;
    const int b = bh >> 2, h = bh & 3;
    const int tid = threadIdx.x;
    const int w = tid >> 5, lane = tid & 31;
    const int wm = w & 3, wn = w >> 2;

    const float* base = qkv + ((long)b * SEQ + segOff) * 768 + h * 64;

    auto loadQ = [&]() {
        const float* Qg = base + (long)qt * 128 * 768;
#pragma unroll
        for (int i = 0; i < 8; i++) {
            int idx = tid + i * 256;
            int r = idx >> 4, c4 = (idx & 15) * 4;
            CPA16(sptr(sQ + r * QLD + c4), Qg + (long)r * 768 + c4);
        }
    };
    auto loadK = [&](int t) {
        const float* Kg = base + 256 + (long)t * 128 * 768;
#pragma unroll
        for (int i = 0; i < 8; i++) {
            int idx = tid + i * 256;
            int r = idx >> 4, c4 = (idx & 15) * 4;
            CPA16(sptr(sK + r * QLD + c4), Kg + (long)r * 768 + c4);
        }
    };
    auto loadV = [&](int t) {
        const float* Vg = base + 512 + (long)t * 128 * 768;
#pragma unroll
        for (int i = 0; i < 8; i++) {
            int idx = tid + i * 256;
            int r = idx >> 4, c4 = (idx & 15) * 4;
            CPA16(sptr(sV + r * QLD + c4), Vg + (long)r * 768 + c4);
        }
    };

    // acc element -> row map (measured by probe kernel)
    int rt[8];
#pragma unroll
    for (int e = 0; e < 8; e++) rt[e] = rowtab[lane * 8 + e];

    if (tid < 128) { mrow[tid] = -1e30f; lrow[tid] = 0.f; }

    loadQ(); loadK(0); CPA_COMMIT();   // group: Q+K0
    loadV(0); CPA_COMMIT();            // group: V0

    wmma::fragment<wmma::accumulator, 16, 16, 8, float> oacc[2][2];
#pragma unroll
    for (int mi = 0; mi < 2; mi++)
#pragma unroll
        for (int ni = 0; ni < 2; ni++) wmma::fill_fragment(oacc[mi][ni], 0.f);

    const int nt = L >> 7;
    for (int t = 0; t < nt; t++) {
        CPA_WAIT1();                  // K[t] (and Q) ready; V[t] may be in flight
        __syncthreads();

        // ---- S = Q @ K^T ----
        {
            wmma::fragment<wmma::accumulator, 16, 16, 8, float> sacc[2][4];
#pragma unroll
            for (int mi = 0; mi < 2; mi++)
#pragma unroll
                for (int ni = 0; ni < 4; ni++) wmma::fill_fragment(sacc[mi][ni], 0.f);
#pragma unroll
            for (int k = 0; k < DH; k += 8) {
                wmma::fragment<wmma::matrix_a, 16, 16, 8, wmma::precision::tf32, wmma::row_major> af[2];
#pragma unroll
                for (int mi = 0; mi < 2; mi++)
                    wmma::load_matrix_sync(af[mi], sQ + (wm * 32 + mi * 16) * QLD + k, QLD);
                wmma::fragment<wmma::matrix_b, 16, 16, 8, wmma::precision::tf32, wmma::col_major> bf[4];
#pragma unroll
                for (int ni = 0; ni < 4; ni++)
                    wmma::load_matrix_sync(bf[ni], sK + (wn * 64 + ni * 16) * QLD + k, QLD);
#pragma unroll
                for (int mi = 0; mi < 2; mi++)
#pragma unroll
                    for (int ni = 0; ni < 4; ni++)
                        wmma::mma_sync(sacc[mi][ni], af[mi], bf[ni], sacc[mi][ni]);
            }
#pragma unroll
            for (int mi = 0; mi < 2; mi++)
#pragma unroll
                for (int ni = 0; ni < 4; ni++)
                    wmma::store_matrix_sync(sS + (wm * 32 + mi * 16) * SLD + wn * 64 + ni * 16,
                                            sacc[mi][ni], SLD, wmma::mem_row_major);
        }
        __syncthreads();              // S visible; all warps done reading sK

        if (t + 1 < nt) { loadK(t + 1); CPA_COMMIT(); }   // overlaps softmax+PV

        // ---- online softmax (2 threads per row) ----
        {
            const int r = tid >> 1, hf = tid & 1;
            float* row = sS + r * SLD + hf * 64;
            float mx = -1e30f;
#pragma unroll 8
            for (int c = 0; c < 64; c++) mx = fmaxf(mx, row[c]);
            mx = fmaxf(mx, __shfl_xor_sync(0xffffffffu, mx, 1));
            mx *= 0.125f;
            float m_old = mrow[r];
            float m_new = fmaxf(m_old, mx);
            float a = __expf(m_old - m_new);
            float sum = 0.f;
#pragma unroll 8
            for (int c = 0; c < 64; c++) {
                float p = __expf(row[c] * 0.125f - m_new);
                row[c] = p;
                sum += p;
            }
            sum += __shfl_xor_sync(0xffffffffu, sum, 1);
            if (hf == 0) {
                mrow[r] = m_new;
                lrow[r] = lrow[r] * a + sum;
                al[r] = a;
            }
        }
        if (t + 1 < nt) { CPA_WAIT1(); } else { CPA_WAIT0(); }   // V[t] ready
        __syncthreads();              // P + al visible

        // ---- rescale O (registers) and accumulate P @ V ----
        {
            float av[2][8];
#pragma unroll
            for (int mi = 0; mi < 2; mi++)
#pragma unroll
                for (int e = 0; e < 8; e++)
                    av[mi][e] = al[wm * 32 + mi * 16 + rt[e]];
#pragma unroll
            for (int mi = 0; mi < 2; mi++)
#pragma unroll
                for (int ni = 0; ni < 2; ni++)
#pragma unroll
                    for (int e = 0; e < 8; e++)
                        oacc[mi][ni].x[e] *= av[mi][e];

#pragma unroll
            for (int k = 0; k < 128; k += 8) {
                wmma::fragment<wmma::matrix_a, 16, 16, 8, wmma::precision::tf32, wmma::row_major> af[2];
#pragma unroll
                for (int mi = 0; mi < 2; mi++)
                    wmma::load_matrix_sync(af[mi], sS + (wm * 32 + mi * 16) * SLD + k, SLD);
                wmma::fragment<wmma::matrix_b, 16, 16, 8, wmma::precision::tf32, wmma::row_major> bf[2];
#pragma unroll
                for (int ni = 0; ni < 2; ni++)
                    wmma::load_matrix_sync(bf[ni], sV + k * QLD + wn * 32 + ni * 16, QLD);
#pragma unroll
                for (int mi = 0; mi < 2; mi++)
#pragma unroll
                    for (int ni = 0; ni < 2; ni++)
                        wmma::mma_sync(oacc[mi][ni], af[mi], bf[ni], oacc[mi][ni]);
            }
        }
        __syncthreads();              // all warps done with sV, sS
        if (t + 1 < nt) { loadV(t + 1); CPA_COMMIT(); }   // overlaps next QK+softmax
    }

    // ---- final: O / l, direct register -> gmem store ----
    if (tid < 128) al[tid] = 1.f / lrow[tid];
    __syncthreads();
    {
        float iv[2][8];
#pragma unroll
        for (int mi = 0; mi < 2; mi++)
#pragma unroll
            for (int e = 0; e < 8; e++)
                iv[mi][e] = al[wm * 32 + mi * 16 + rt[e]];
        float* outp = ctx + ((long)b * SEQ + segOff + (long)qt * 128) * HID + h * 64;
#pragma unroll
        for (int mi = 0; mi < 2; mi++)
#pragma unroll
            for (int ni = 0; ni < 2; ni++) {
#pragma unroll
                for (int e = 0; e < 8; e++) oacc[mi][ni].x[e] *= iv[mi][e];
                wmma::store_matrix_sync(
                    outp + (long)(wm * 32 + mi * 16) * HID + wn * 32 + ni * 16,
                    oacc[mi][ni], HID, wmma::mem_row_major);
            }
    }
}

// -------------------- small kernels -----------------------------------------
__global__ void pad_w1_k(const float* __restrict__ w, float* __restrict__ o)
{
    int i = blockIdx.x * 256 + threadIdx.x;
    int r = i >> 9, c = i & 511;
    o[i] = (c < 400) ? w[r * 400 + c] : 0.f;
}
__global__ void pad_b1_k(const float* __restrict__ b, float* __restrict__ o)
{
    int c = threadIdx.x + blockIdx.x * 256;
    o[c] = (c < 400) ? b[c] : 0.f;
}
__global__ void pad_w2_k(const float* __restrict__ w, float* __restrict__ o)
{
    int i = blockIdx.x * 256 + threadIdx.x;
    int r = i >> 8, c = i & 255;
    o[i] = (r < 400) ? w[r * 256 + c] : 0.f;
}

__global__ void zero_mean_k(float* __restrict__ m)
{
    m[blockIdx.x * 256 + threadIdx.x] = 0.f;
}

__global__ void mean_part_k(const float* __restrict__ x, float* __restrict__ mout)
{
    int seg = blockIdx.x, part = blockIdx.y;
    int b = seg / 3, sgi = seg % 3;
    int off = (sgi == 0) ? 0 : (sgi == 1 ? 512 : 768);
    int L   = (sgi == 0) ? 512 : 256;
    int rows = L >> 3;
    int t = threadIdx.x;
    const float* p = x + ((long)b * SEQ + off + part * rows) * HID + t;
    float s = 0.f;
    for (int i = 0; i < rows; i++) s += p[(long)i * HID];
    atomicAdd(&mout[(long)seg * HID + t], s);
}

__global__ void final_k(const float* __restrict__ mean, const float* __restrict__ W,
                        const float* __restrict__ bias, float* __restrict__ out)
{
    int b = blockIdx.x, n = threadIdx.x;
    __shared__ float comb[HID];
    const float* mp = mean + (long)b * 3 * HID;
    comb[n] = mp[n] * (1.f / 512.f) - mp[HID + n] * (1.f / 256.f)
            + mp[2 * HID + n] * (1.f / 256.f);
    __syncthreads();
    float s = bias[n];
#pragma unroll 8
    for (int k = 0; k < HID; k++) s += comb[k] * W[k * HID + n];
    out[(long)b * HID + n] = fmaxf(s, 0.f);
}

// ---------------------------------------------------------------------------
static void launch_gemm(const float* A, const float* B, const float* bias, float* C,
                        int M, int N, int K, int lda, int ldb, int ldc,
                        long sAb, long sBb, long sCb, int batches, int relu,
                        const int* aidx = nullptr)
{
    dim3 grid(N / BN, M / BM, batches);
    gemm_tc<<<grid, 128, GEMM_SMEM_BYTES>>>(A, B, bias, C, K, lda, ldb, ldc,
                                            sAb, sBb, sCb, relu, aidx);
}

extern "C" void kernel_launch(void* const* d_in, const int* in_sizes, int n_in,
                              void* d_out, int out_size)
{
    const int*   hyper = (const int*)  d_in[0];
    const float* HT    = (const float*)d_in[1];
    const float* emb   = (const float*)d_in[2];
    const float* Wg1   = (const float*)d_in[3];
    const float* bg1   = (const float*)d_in[4];
    const float* Wg2   = (const float*)d_in[5];
    const float* bg2   = (const float*)d_in[6];
    const float* Wqkv  = (const float*)d_in[7];
    const float* bqkv  = (const float*)d_in[8];
    const float* Wo    = (const float*)d_in[9];
    const float* bo    = (const float*)d_in[10];
    const float* ln1g  = (const float*)d_in[11];
    const float* ln1b  = (const float*)d_in[12];
    const float* Wff1  = (const float*)d_in[13];
    const float* bff1  = (const float*)d_in[14];
    const float* Wff2  = (const float*)d_in[15];
    const float* bff2  = (const float*)d_in[16];
    const float* ln2g  = (const float*)d_in[17];
    const float* ln2b  = (const float*)d_in[18];
    const float* fc1W  = (const float*)d_in[19];
    const float* fc1b  = (const float*)d_in[20];

    float *t, *x, *x1, *qkv, *ctx, *ff, *mean, *w1p, *b1p, *w2p;
    int* rowtab;
    cudaGetSymbolAddress((void**)&t,      g_t);
    cudaGetSymbolAddress((void**)&x,      g_x);
    cudaGetSymbolAddress((void**)&x1,     g_x1);
    cudaGetSymbolAddress((void**)&qkv,    g_qkv);
    cudaGetSymbolAddress((void**)&ctx,    g_ctx);
    cudaGetSymbolAddress((void**)&ff,     g_ff);
    cudaGetSymbolAddress((void**)&mean,   g_mean);
    cudaGetSymbolAddress((void**)&w1p,    g_w1p);
    cudaGetSymbolAddress((void**)&b1p,    g_b1p);
    cudaGetSymbolAddress((void**)&w2p,    g_w2p);
    cudaGetSymbolAddress((void**)&rowtab, g_rowtab);

    cudaFuncSetAttribute(flash_k, cudaFuncAttributeMaxDynamicSharedMemorySize,
                         FLASH_SMEM_BYTES);
    cudaFuncSetAttribute(gemm_tc, cudaFuncAttributeMaxDynamicSharedMemorySize,
                         GEMM_SMEM_BYTES);
    cudaFuncSetAttribute(gemm_ln, cudaFuncAttributeMaxDynamicSharedMemorySize,
                         LN_SMEM_BYTES);

    // 0. probe acc layout + pad FF weights
    probe_k<<<1, 32>>>(rowtab);
    pad_w1_k<<<HID * FFP / 256, 256>>>(Wff1, w1p);
    pad_b1_k<<<2, 256>>>(bff1, b1p);
    pad_w2_k<<<FFP * HID / 256, 256>>>(Wff2, w2p);

    // 1. t = emb[hyper] @ Wg1   (gather fused)
    launch_gemm(emb, Wg1, nullptr, t, TOKENS, HID, HID, HID, HID, HID,
                0, 0, 0, 1, 0, hyper);

    // 2. x = batched HT @ t + bg1
    launch_gemm(HT, t, bg1, x, SEQ, HID, SEQ, SEQ, HID, HID,
                (long)SEQ * SEQ, (long)SEQ * HID, (long)SEQ * HID, NB, 0);

    // 3. t = x @ Wg2
    launch_gemm(x, Wg2, nullptr, t, TOKENS, HID, HID, HID, HID, HID, 0, 0, 0, 1, 0);

    // 4. x = batched HT @ t + bg2
    launch_gemm(HT, t, bg2, x, SEQ, HID, SEQ, SEQ, HID, HID,
                (long)SEQ * SEQ, (long)SEQ * HID, (long)SEQ * HID, NB, 0);

    // 5. qkv = x @ Wqkv + bqkv
    launch_gemm(x, Wqkv, bqkv, qkv, TOKENS, 3 * HID, HID, HID, 3 * HID, 3 * HID,
                0, 0, 0, 1, 0);

    // 6. fused flash attention — single launch, all segments
    flash_k<<<dim3(8, NB * NHEADS), 256, FLASH_SMEM_BYTES>>>(qkv, ctx, rowtab);

    // 7. x1 = LN1(x + ctx @ Wo + bo)
    gemm_ln<<<TOKENS / LBM, 256, LN_SMEM_BYTES>>>(ctx, Wo, bo, x, ln1g, ln1b,
                                                  x1, HID, HID);

    // 8. ff = relu(x1 @ w1p + b1p)
    launch_gemm(x1, w1p, b1p, ff, TOKENS, FFP, HID, HID, FFP, FFP, 0, 0, 0, 1, 1);

    // 9. x = LN2(x1 + ff @ w2p + bff2)
    gemm_ln<<<TOKENS / LBM, 256, LN_SMEM_BYTES>>>(ff, w2p, bff2, x1, ln2g, ln2b,
                                                  x, FFP, FFP);

    // 10. segment means (two-stage)
    zero_mean_k<<<NB * 3, 256>>>(mean);
    mean_part_k<<<dim3(NB * 3, 8), 256>>>(x, mean);

    // 11. out = relu((p - n + f) @ fc1W + fc1b)
    final_k<<<NB, 256>>>(mean, fc1W, fc1b, (float*)d_out);
}

// round 9
// speedup vs baseline: 1.0426x; 1.0015x over previous
#include <cuda_runtime.h>
#include <cuda_bf16.h>
#include <mma.h>

using namespace nvcuda;

// ---------------------------------------------------------------------------
// GraphEncoder: tf32 TC GEMMs + flash attention with FMA-pipe exp2 softmax.
// Shapes: B=16, S=1024 (segments 512/256/256), H=256, heads=4 (Dh=64), F=400.
// ---------------------------------------------------------------------------

#define NB 16
#define SEQ 1024
#define HID 256
#define NHEADS 4
#define DH 64
#define FFP 512
#define TOKENS (NB * SEQ)

// -------------------- scratch (device globals; no allocation) --------------
__device__ float g_t[TOKENS * HID];
__device__ float g_x[TOKENS * HID];
__device__ float g_x1[TOKENS * HID];
__device__ float g_qkv[TOKENS * 3 * HID];
__device__ float g_ctx[TOKENS * HID];
__device__ float g_ff[TOKENS * FFP];
__device__ float g_mean[NB * 3 * HID];
__device__ float g_w1p[HID * FFP];
__device__ float g_b1p[FFP];
__device__ float g_w2p[FFP * HID];
__device__ int   g_rowtab[256];          // wmma acc element -> row map

__device__ __forceinline__ unsigned sptr(const void* p) {
    return (unsigned)__cvta_generic_to_shared(p);
}
#define CPA16(dst, src) asm volatile("cp.async.ca.shared.global [%0], [%1], 16;" :: "r"(dst), "l"(src))
#define CPA_COMMIT()    asm volatile("cp.async.commit_group;")
#define CPA_WAIT0()     asm volatile("cp.async.wait_group 0;")
#define CPA_WAIT1()     asm volatile("cp.async.wait_group 1;")

// FMA-pipe exp2: no MUFU. Valid for y <= ~0 (clamped at -80 -> ~8e-25).
// rel err ~4e-5 (degree-4 Taylor of 2^f on [-0.5, 0.5]).
__device__ __forceinline__ float fexp2(float y) {
    y = fmaxf(y, -80.f);
    float t = y + 12582912.f;                       // 1.5 * 2^23 round magic
    int   n = __float_as_int(t) - 0x4B400000;       // integer part
    float f = y - (t - 12582912.f);                 // f in [-0.5, 0.5]
    float p = 1.f + f * (0.69314718f + f * (0.24022651f +
                   f * (0.05550411f + f * 0.00961813f)));
    return __int_as_float(__float_as_int(p) + (n << 23));
}
#define SM_SCALE 0.18033688f   // 0.125 * log2(e): softmax done in exp2 domain

// -------------------- probe: measure wmma fp32 acc element->row map --------
__global__ void probe_k(int* __restrict__ rowtab)
{
    __shared__ float pat[16 * 16];
    int lane = threadIdx.x;
    for (int i = lane; i < 256; i += 32) pat[i] = (float)(i >> 4);
    __syncwarp();
    wmma::fragment<wmma::accumulator, 16, 16, 8, float> f;
    wmma::load_matrix_sync(f, pat, 16, wmma::mem_row_major);
#pragma unroll
    for (int e = 0; e < f.num_elements && e < 8; e++)
        rowtab[lane * 8 + e] = (int)f.x[e];
}

// -------------------- generic tf32 GEMM (128x128 CTA, 128 thr) -------------
#define BM 128
#define BN 128
#define BK 16
#define APAD 20
#define BPAD 132
#define AS_STAGE (BM * APAD)
#define BS_STAGE (BK * BPAD)
#define STAGES 3
#define BIAS_OFF (STAGES * (AS_STAGE + BS_STAGE))
#define GEMM_SMEM_BYTES ((BIAS_OFF + 16 * BPAD) * 4)

__global__ void __launch_bounds__(128, 2) gemm_tc(
    const float* __restrict__ A, const float* __restrict__ Bm,
    const float* __restrict__ bias, float* __restrict__ C,
    int K, int lda, int ldb, int ldc,
    long sAb, long sBb, long sCb, int relu, const int* __restrict__ aidx)
{
    extern __shared__ float sm[];

    const int z = blockIdx.z;
    A  += (long)z * sAb;
    Bm += (long)z * sBb;
    C  += (long)z * sCb;

    const int tid = threadIdx.x;
    const int w = tid >> 5;
    const int wm = w & 1, wn = w >> 1;
    const int rowTile = blockIdx.y * BM;
    const int colTile = blockIdx.x * BN;

    auto loadA = [&](int kt, int s) {
        float* sa = sm + s * AS_STAGE;
        if (aidx) {
#pragma unroll
            for (int i = 0; i < 4; i++) {
                int idx = tid + i * 128;
                int r = idx >> 2, c4 = (idx & 3) * 4;
                long row = aidx[rowTile + r];
                CPA16(sptr(sa + r * APAD + c4), A + row * lda + kt * BK + c4);
            }
        } else {
            const float* Ag = A + (long)rowTile * lda + kt * BK;
#pragma unroll
            for (int i = 0; i < 4; i++) {
                int idx = tid + i * 128;
                int r = idx >> 2, c4 = (idx & 3) * 4;
                CPA16(sptr(sa + r * APAD + c4), Ag + (long)r * lda + c4);
            }
        }
    };
    auto loadB = [&](int kt, int s) {
        const float* Bg = Bm + (long)(kt * BK) * ldb + colTile;
        float* sb = sm + STAGES * AS_STAGE + s * BS_STAGE;
#pragma unroll
        for (int i = 0; i < 4; i++) {
            int idx = tid + i * 128;
            int r = idx >> 5, c4 = (idx & 31) * 4;
            CPA16(sptr(sb + r * BPAD + c4), Bg + (long)r * ldb + c4);
        }
    };

    float* biasm = sm + BIAS_OFF;
    if (bias) {
        for (int i = tid; i < 16 * 128; i += 128) {
            int r = i >> 7, c = i & 127;
            biasm[r * BPAD + c] = bias[colTile + c];
        }
    }

    loadA(0, 0); loadB(0, 0); CPA_COMMIT();
    loadA(1, 1); loadB(1, 1); CPA_COMMIT();
    __syncthreads();

    wmma::fragment<wmma::accumulator, 16, 16, 8, float> acc[4][4];
    if (bias) {
#pragma unroll
        for (int ni = 0; ni < 4; ni++) {
            wmma::load_matrix_sync(acc[0][ni], biasm + wn * 64 + ni * 16, BPAD,
                                   wmma::mem_row_major);
#pragma unroll
            for (int mi = 1; mi < 4; mi++) acc[mi][ni] = acc[0][ni];
        }
    } else {
#pragma unroll
        for (int mi = 0; mi < 4; mi++)
#pragma unroll
            for (int ni = 0; ni < 4; ni++) wmma::fill_fragment(acc[mi][ni], 0.f);
    }

    const int nk = K / BK;
    for (int kt = 0; kt < nk; kt++) {
        CPA_WAIT1();
        __syncthreads();
        if (kt + 2 < nk) { int s = (kt + 2) % STAGES; loadA(kt + 2, s); loadB(kt + 2, s); CPA_COMMIT(); }

        const float* sa = sm + (kt % STAGES) * AS_STAGE;
        const float* sb = sm + STAGES * AS_STAGE + (kt % STAGES) * BS_STAGE;

#pragma unroll
        for (int ks = 0; ks < 2; ks++) {
            wmma::fragment<wmma::matrix_a, 16, 16, 8, wmma::precision::tf32, wmma::row_major> af[4];
#pragma unroll
            for (int mi = 0; mi < 4; mi++)
                wmma::load_matrix_sync(af[mi], sa + (wm * 64 + mi * 16) * APAD + ks * 8, APAD);
            wmma::fragment<wmma::matrix_b, 16, 16, 8, wmma::precision::tf32, wmma::row_major> bf[4];
#pragma unroll
            for (int ni = 0; ni < 4; ni++)
                wmma::load_matrix_sync(bf[ni], sb + (ks * 8) * BPAD + wn * 64 + ni * 16, BPAD);
#pragma unroll
            for (int mi = 0; mi < 4; mi++)
#pragma unroll
                for (int ni = 0; ni < 4; ni++)
                    wmma::mma_sync(acc[mi][ni], af[mi], bf[ni], acc[mi][ni]);
        }
    }

#pragma unroll
    for (int mi = 0; mi < 4; mi++)
#pragma unroll
        for (int ni = 0; ni < 4; ni++) {
            if (relu)
#pragma unroll
                for (int e = 0; e < acc[mi][ni].num_elements; e++)
                    acc[mi][ni].x[e] = fmaxf(acc[mi][ni].x[e], 0.f);
            wmma::store_matrix_sync(
                C + (long)(rowTile + wm * 64 + mi * 16) * ldc + colTile + wn * 64 + ni * 16,
                acc[mi][ni], ldc, wmma::mem_row_major);
        }
}

// -------------------- GEMM + residual + LayerNorm fused --------------------
#define LBM 128
#define LAPAD 20
#define LBPAD 260
#define LAS_STAGE (LBM * LAPAD)
#define LBS_STAGE (BK * LBPAD)
#define LEPI_OFF (STAGES * (LAS_STAGE + LBS_STAGE))
#define LN_SMEM_BYTES ((LEPI_OFF + LBM * LBPAD + 2 * LBM) * 4)

__global__ void __launch_bounds__(256, 1) gemm_ln(
    const float* __restrict__ A, const float* __restrict__ Bm,
    const float* __restrict__ bias, const float* __restrict__ res,
    const float* __restrict__ lng, const float* __restrict__ lnb,
    float* __restrict__ out, int K, int lda)
{
    extern __shared__ float sm[];
    float* epi = sm + LEPI_OFF;
    float* smu = epi + LBM * LBPAD;
    float* srs = smu + LBM;

    const int tid = threadIdx.x;
    const int w = tid >> 5;
    const int wm = w & 1, wn = w >> 1;
    const int rowTile = blockIdx.x * LBM;

    auto loadA = [&](int kt, int s) {
        const float* Ag = A + (long)rowTile * lda + kt * BK;
        float* sa = sm + s * LAS_STAGE;
#pragma unroll
        for (int i = 0; i < 2; i++) {
            int idx = tid + i * 256;
            int r = idx >> 2, c4 = (idx & 3) * 4;
            CPA16(sptr(sa + r * LAPAD + c4), Ag + (long)r * lda + c4);
        }
    };
    auto loadB = [&](int kt, int s) {
        const float* Bg = Bm + (long)(kt * BK) * 256;
        float* sb = sm + STAGES * LAS_STAGE + s * LBS_STAGE;
#pragma unroll
        for (int i = 0; i < 4; i++) {
            int idx = tid + i * 256;
            int r = idx >> 6, c4 = (idx & 63) * 4;
            CPA16(sptr(sb + r * LBPAD + c4), Bg + (long)r * 256 + c4);
        }
    };

    loadA(0, 0); loadB(0, 0); CPA_COMMIT();
    loadA(1, 1); loadB(1, 1); CPA_COMMIT();

    wmma::fragment<wmma::accumulator, 16, 16, 8, float> acc[4][4];
#pragma unroll
    for (int mi = 0; mi < 4; mi++)
#pragma unroll
        for (int ni = 0; ni < 4; ni++) wmma::fill_fragment(acc[mi][ni], 0.f);

    const int nk = K / BK;
    for (int kt = 0; kt < nk; kt++) {
        CPA_WAIT1();
        __syncthreads();
        if (kt + 2 < nk) { int s = (kt + 2) % STAGES; loadA(kt + 2, s); loadB(kt + 2, s); CPA_COMMIT(); }

        const float* sa = sm + (kt % STAGES) * LAS_STAGE;
        const float* sb = sm + STAGES * LAS_STAGE + (kt % STAGES) * LBS_STAGE;

#pragma unroll
        for (int ks = 0; ks < 2; ks++) {
            wmma::fragment<wmma::matrix_a, 16, 16, 8, wmma::precision::tf32, wmma::row_major> af[4];
#pragma unroll
            for (int mi = 0; mi < 4; mi++)
                wmma::load_matrix_sync(af[mi], sa + (wm * 64 + mi * 16) * LAPAD + ks * 8, LAPAD);
            wmma::fragment<wmma::matrix_b, 16, 16, 8, wmma::precision::tf32, wmma::row_major> bf[4];
#pragma unroll
            for (int ni = 0; ni < 4; ni++)
                wmma::load_matrix_sync(bf[ni], sb + (ks * 8) * LBPAD + wn * 64 + ni * 16, LBPAD);
#pragma unroll
            for (int mi = 0; mi < 4; mi++)
#pragma unroll
                for (int ni = 0; ni < 4; ni++)
                    wmma::mma_sync(acc[mi][ni], af[mi], bf[ni], acc[mi][ni]);
        }
    }
    __syncthreads();

#pragma unroll
    for (int mi = 0; mi < 4; mi++)
#pragma unroll
        for (int ni = 0; ni < 4; ni++)
            wmma::store_matrix_sync(epi + (wm * 64 + mi * 16) * LBPAD + wn * 64 + ni * 16,
                                    acc[mi][ni], LBPAD, wmma::mem_row_major);
    __syncthreads();

#pragma unroll 8
    for (int i = 0; i < 128; i++) {
        int idx = tid + i * 256;
        int r = idx >> 8, c = idx & 255;
        epi[r * LBPAD + c] += bias[c] + res[(long)(rowTile + r) * HID + c];
    }
    __syncthreads();

    {
        const int r = tid >> 1, hf = tid & 1;
        const float* row = epi + r * LBPAD + hf * 128;
        float s = 0.f, s2 = 0.f;
#pragma unroll 8
        for (int c = 0; c < 128; c++) { float v = row[c]; s += v; s2 += v * v; }
        s  += __shfl_xor_sync(0xffffffffu, s, 1);
        s2 += __shfl_xor_sync(0xffffffffu, s2, 1);
        if (hf == 0) {
            float mu = s * (1.f / 256.f);
            float var = s2 * (1.f / 256.f) - mu * mu;
            smu[r] = mu;
            srs[r] = rsqrtf(var + 1e-5f);
        }
    }
    __syncthreads();

#pragma unroll 8
    for (int i = 0; i < 128; i++) {
        int idx = tid + i * 256;
        int r = idx >> 8, c = idx & 255;
        float v = (epi[r * LBPAD + c] - smu[r]) * srs[r] * lng[c] + lnb[c];
        out[(long)(rowTile + r) * HID + c] = v;
    }
}

// -------------------- flash attention (O in registers, fexp2 softmax) ------
#define QLD 68
#define SLD 132
#define FS_Q 0
#define FS_K 8704
#define FS_V 17408
#define FS_S 26112
#define FS_AL 43008
#define FS_M 43136
#define FS_L 43264
#define FLASH_SMEM_BYTES (43392 * 4)

__global__ void __launch_bounds__(256) flash_k(
    const float* __restrict__ qkv, float* __restrict__ ctx,
    const int* __restrict__ rowtab)
{
    extern __shared__ float sm[];
    float* sQ = sm + FS_Q;
    float* sK = sm + FS_K;
    float* sV = sm + FS_V;
    float* sS = sm + FS_S;
    float* al = sm + FS_AL;
    float* mrow = sm + FS_M;
    float* lrow = sm + FS_L;

    const int bx = blockIdx.x;
    int segOff, L, qt;
    if (bx < 4)      { segOff = 0;   L = 512; qt = bx; }
    else if (bx < 6) { segOff = 512; L = 256; qt = bx - 4; }
    else             { segOff = 768; L = 256; qt = bx - 6; }

    const int bh = blockIdx.y;
    const int b = bh >> 2, h = bh & 3;
    const int tid = threadIdx.x;
    const int w = tid >> 5, lane = tid & 31;
    const int wm = w & 3, wn = w >> 2;

    const float* base = qkv + ((long)b * SEQ + segOff) * 768 + h * 64;

    auto loadQ = [&]() {
        const float* Qg = base + (long)qt * 128 * 768;
#pragma unroll
        for (int i = 0; i < 8; i++) {
            int idx = tid + i * 256;
            int r = idx >> 4, c4 = (idx & 15) * 4;
            CPA16(sptr(sQ + r * QLD + c4), Qg + (long)r * 768 + c4);
        }
    };
    auto loadK = [&](int t) {
        const float* Kg = base + 256 + (long)t * 128 * 768;
#pragma unroll
        for (int i = 0; i < 8; i++) {
            int idx = tid + i * 256;
            int r = idx >> 4, c4 = (idx & 15) * 4;
            CPA16(sptr(sK + r * QLD + c4), Kg + (long)r * 768 + c4);
        }
    };
    auto loadV = [&](int t) {
        const float* Vg = base + 512 + (long)t * 128 * 768;
#pragma unroll
        for (int i = 0; i < 8; i++) {
            int idx = tid + i * 256;
            int r = idx >> 4, c4 = (idx & 15) * 4;
            CPA16(sptr(sV + r * QLD + c4), Vg + (long)r * 768 + c4);
        }
    };

    int rt[8];
#pragma unroll
    for (int e = 0; e < 8; e++) rt[e] = rowtab[lane * 8 + e];

    if (tid < 128) { mrow[tid] = -1e30f; lrow[tid] = 0.f; }

    loadQ(); loadK(0); CPA_COMMIT();
    loadV(0); CPA_COMMIT();

    wmma::fragment<wmma::accumulator, 16, 16, 8, float> oacc[2][2];
#pragma unroll
    for (int mi = 0; mi < 2; mi++)
#pragma unroll
        for (int ni = 0; ni < 2; ni++) wmma::fill_fragment(oacc[mi][ni], 0.f);

    const int nt = L >> 7;
    for (int t = 0; t < nt; t++) {
        CPA_WAIT1();
        __syncthreads();

        // ---- S = Q @ K^T ----
        {
            wmma::fragment<wmma::accumulator, 16, 16, 8, float> sacc[2][4];
#pragma unroll
            for (int mi = 0; mi < 2; mi++)
#pragma unroll
                for (int ni = 0; ni < 4; ni++) wmma::fill_fragment(sacc[mi][ni], 0.f);
#pragma unroll
            for (int k = 0; k < DH; k += 8) {
                wmma::fragment<wmma::matrix_a, 16, 16, 8, wmma::precision::tf32, wmma::row_major> af[2];
#pragma unroll
                for (int mi = 0; mi < 2; mi++)
                    wmma::load_matrix_sync(af[mi], sQ + (wm * 32 + mi * 16) * QLD + k, QLD);
                wmma::fragment<wmma::matrix_b, 16, 16, 8, wmma::precision::tf32, wmma::col_major> bf[4];
#pragma unroll
                for (int ni = 0; ni < 4; ni++)
                    wmma::load_matrix_sync(bf[ni], sK + (wn * 64 + ni * 16) * QLD + k, QLD);
#pragma unroll
                for (int mi = 0; mi < 2; mi++)
#pragma unroll
                    for (int ni = 0; ni < 4; ni++)
                        wmma::mma_sync(sacc[mi][ni], af[mi], bf[ni], sacc[mi][ni]);
            }
#pragma unroll
            for (int mi = 0; mi < 2; mi++)
#pragma unroll
                for (int ni = 0; ni < 4; ni++)
                    wmma::store_matrix_sync(sS + (wm * 32 + mi * 16) * SLD + wn * 64 + ni * 16,
                                            sacc[mi][ni], SLD, wmma::mem_row_major);
        }
        __syncthreads();

        if (t + 1 < nt) { loadK(t + 1); CPA_COMMIT(); }

        // ---- online softmax in exp2 domain (FMA-pipe, no MUFU) ----
        {
            const int r = tid >> 1, hf = tid & 1;
            float* row = sS + r * SLD + hf * 64;
            float mx = -1e30f;
#pragma unroll 8
            for (int c = 0; c < 64; c++) mx = fmaxf(mx, row[c]);
            mx = fmaxf(mx, __shfl_xor_sync(0xffffffffu, mx, 1));
            mx *= SM_SCALE;                      // exp2-domain max
            float m_old = mrow[r];
            float m_new = fmaxf(m_old, mx);
            float a = fexp2(m_old - m_new);
            float sum = 0.f;
#pragma unroll 4
            for (int c = 0; c < 64; c++) {
                float p = fexp2(row[c] * SM_SCALE - m_new);
                row[c] = p;
                sum += p;
            }
            sum += __shfl_xor_sync(0xffffffffu, sum, 1);
            if (hf == 0) {
                mrow[r] = m_new;
                lrow[r] = lrow[r] * a + sum;
                al[r] = a;
            }
        }
        if (t + 1 < nt) { CPA_WAIT1(); } else { CPA_WAIT0(); }
        __syncthreads();

        // ---- rescale O and accumulate P @ V ----
        {
            float av[2][8];
#pragma unroll
            for (int mi = 0; mi < 2; mi++)
#pragma unroll
                for (int e = 0; e < 8; e++)
                    av[mi][e] = al[wm * 32 + mi * 16 + rt[e]];
#pragma unroll
            for (int mi = 0; mi < 2; mi++)
#pragma unroll
                for (int ni = 0; ni < 2; ni++)
#pragma unroll
                    for (int e = 0; e < 8; e++)
                        oacc[mi][ni].x[e] *= av[mi][e];

#pragma unroll
            for (int k = 0; k < 128; k += 8) {
                wmma::fragment<wmma::matrix_a, 16, 16, 8, wmma::precision::tf32, wmma::row_major> af[2];
#pragma unroll
                for (int mi = 0; mi < 2; mi++)
                    wmma::load_matrix_sync(af[mi], sS + (wm * 32 + mi * 16) * SLD + k, SLD);
                wmma::fragment<wmma::matrix_b, 16, 16, 8, wmma::precision::tf32, wmma::row_major> bf[2];
#pragma unroll
                for (int ni = 0; ni < 2; ni++)
                    wmma::load_matrix_sync(bf[ni], sV + k * QLD + wn * 32 + ni * 16, QLD);
#pragma unroll
                for (int mi = 0; mi < 2; mi++)
#pragma unroll
                    for (int ni = 0; ni < 2; ni++)
                        wmma::mma_sync(oacc[mi][ni], af[mi], bf[ni], oacc[mi][ni]);
            }
        }
        __syncthreads();
        if (t + 1 < nt) { loadV(t + 1); CPA_COMMIT(); }
    }

    if (tid < 128) al[tid] = 1.f / lrow[tid];
    __syncthreads();
    {
        float iv[2][8];
#pragma unroll
        for (int mi = 0; mi < 2; mi++)
#pragma unroll
            for (int e = 0; e < 8; e++)
                iv[mi][e] = al[wm * 32 + mi * 16 + rt[e]];
        float* outp = ctx + ((long)b * SEQ + segOff + (long)qt * 128) * HID + h * 64;
#pragma unroll
        for (int mi = 0; mi < 2; mi++)
#pragma unroll
            for (int ni = 0; ni < 2; ni++) {
#pragma unroll
                for (int e = 0; e < 8; e++) oacc[mi][ni].x[e] *= iv[mi][e];
                wmma::store_matrix_sync(
                    outp + (long)(wm * 32 + mi * 16) * HID + wn * 32 + ni * 16,
                    oacc[mi][ni], HID, wmma::mem_row_major);
            }
    }
}

// -------------------- small kernels -----------------------------------------
__global__ void pad_w1_k(const float* __restrict__ w, float* __restrict__ o)
{
    int i = blockIdx.x * 256 + threadIdx.x;
    int r = i >> 9, c = i & 511;
    o[i] = (c < 400) ? w[r * 400 + c] : 0.f;
}
__global__ void pad_b1_k(const float* __restrict__ b, float* __restrict__ o)
{
    int c = threadIdx.x + blockIdx.x * 256;
    o[c] = (c < 400) ? b[c] : 0.f;
}
__global__ void pad_w2_k(const float* __restrict__ w, float* __restrict__ o)
{
    int i = blockIdx.x * 256 + threadIdx.x;
    int r = i >> 8, c = i & 255;
    o[i] = (r < 400) ? w[r * 256 + c] : 0.f;
}

__global__ void zero_mean_k(float* __restrict__ m)
{
    m[blockIdx.x * 256 + threadIdx.x] = 0.f;
}

__global__ void mean_part_k(const float* __restrict__ x, float* __restrict__ mout)
{
    int seg = blockIdx.x, part = blockIdx.y;
    int b = seg / 3, sgi = seg % 3;
    int off = (sgi == 0) ? 0 : (sgi == 1 ? 512 : 768);
    int L   = (sgi == 0) ? 512 : 256;
    int rows = L >> 3;
    int t = threadIdx.x;
    const float* p = x + ((long)b * SEQ + off + part * rows) * HID + t;
    float s = 0.f;
    for (int i = 0; i < rows; i++) s += p[(long)i * HID];
    atomicAdd(&mout[(long)seg * HID + t], s);
}

__global__ void final_k(const float* __restrict__ mean, const float* __restrict__ W,
                        const float* __restrict__ bias, float* __restrict__ out)
{
    int b = blockIdx.x, n = threadIdx.x;
    __shared__ float comb[HID];
    const float* mp = mean + (long)b * 3 * HID;
    comb[n] = mp[n] * (1.f / 512.f) - mp[HID + n] * (1.f / 256.f)
            + mp[2 * HID + n] * (1.f / 256.f);
    __syncthreads();
    float s = bias[n];
#pragma unroll 8
    for (int k = 0; k < HID; k++) s += comb[k] * W[k * HID + n];
    out[(long)b * HID + n] = fmaxf(s, 0.f);
}

// ---------------------------------------------------------------------------
static void launch_gemm(const float* A, const float* B, const float* bias, float* C,
                        int M, int N, int K, int lda, int ldb, int ldc,
                        long sAb, long sBb, long sCb, int batches, int relu,
                        const int* aidx = nullptr)
{
    dim3 grid(N / BN, M / BM, batches);
    gemm_tc<<<grid, 128, GEMM_SMEM_BYTES>>>(A, B, bias, C, K, lda, ldb, ldc,
                                            sAb, sBb, sCb, relu, aidx);
}

extern "C" void kernel_launch(void* const* d_in, const int* in_sizes, int n_in,
                              void* d_out, int out_size)
{
    const int*   hyper = (const int*)  d_in[0];
    const float* HT    = (const float*)d_in[1];
    const float* emb   = (const float*)d_in[2];
    const float* Wg1   = (const float*)d_in[3];
    const float* bg1   = (const float*)d_in[4];
    const float* Wg2   = (const float*)d_in[5];
    const float* bg2   = (const float*)d_in[6];
    const float* Wqkv  = (const float*)d_in[7];
    const float* bqkv  = (const float*)d_in[8];
    const float* Wo    = (const float*)d_in[9];
    const float* bo    = (const float*)d_in[10];
    const float* ln1g  = (const float*)d_in[11];
    const float* ln1b  = (const float*)d_in[12];
    const float* Wff1  = (const float*)d_in[13];
    const float* bff1  = (const float*)d_in[14];
    const float* Wff2  = (const float*)d_in[15];
    const float* bff2  = (const float*)d_in[16];
    const float* ln2g  = (const float*)d_in[17];
    const float* ln2b  = (const float*)d_in[18];
    const float* fc1W  = (const float*)d_in[19];
    const float* fc1b  = (const float*)d_in[20];

    float *t, *x, *x1, *qkv, *ctx, *ff, *mean, *w1p, *b1p, *w2p;
    int* rowtab;
    cudaGetSymbolAddress((void**)&t,      g_t);
    cudaGetSymbolAddress((void**)&x,      g_x);
    cudaGetSymbolAddress((void**)&x1,     g_x1);
    cudaGetSymbolAddress((void**)&qkv,    g_qkv);
    cudaGetSymbolAddress((void**)&ctx,    g_ctx);
    cudaGetSymbolAddress((void**)&ff,     g_ff);
    cudaGetSymbolAddress((void**)&mean,   g_mean);
    cudaGetSymbolAddress((void**)&w1p,    g_w1p);
    cudaGetSymbolAddress((void**)&b1p,    g_b1p);
    cudaGetSymbolAddress((void**)&w2p,    g_w2p);
    cudaGetSymbolAddress((void**)&rowtab, g_rowtab);

    cudaFuncSetAttribute(flash_k, cudaFuncAttributeMaxDynamicSharedMemorySize,
                         FLASH_SMEM_BYTES);
    cudaFuncSetAttribute(gemm_tc, cudaFuncAttributeMaxDynamicSharedMemorySize,
                         GEMM_SMEM_BYTES);
    cudaFuncSetAttribute(gemm_ln, cudaFuncAttributeMaxDynamicSharedMemorySize,
                         LN_SMEM_BYTES);

    // 0. probe acc layout + pad FF weights
    probe_k<<<1, 32>>>(rowtab);
    pad_w1_k<<<HID * FFP / 256, 256>>>(Wff1, w1p);
    pad_b1_k<<<2, 256>>>(bff1, b1p);
    pad_w2_k<<<FFP * HID / 256, 256>>>(Wff2, w2p);

    // 1. t = emb[hyper] @ Wg1   (gather fused)
    launch_gemm(emb, Wg1, nullptr, t, TOKENS, HID, HID, HID, HID, HID,
                0, 0, 0, 1, 0, hyper);

    // 2. x = batched HT @ t + bg1
    launch_gemm(HT, t, bg1, x, SEQ, HID, SEQ, SEQ, HID, HID,
                (long)SEQ * SEQ, (long)SEQ * HID, (long)SEQ * HID, NB, 0);

    // 3. t = x @ Wg2
    launch_gemm(x, Wg2, nullptr, t, TOKENS, HID, HID, HID, HID, HID, 0, 0, 0, 1, 0);

    // 4. x = batched HT @ t + bg2
    launch_gemm(HT, t, bg2, x, SEQ, HID, SEQ, SEQ, HID, HID,
                (long)SEQ * SEQ, (long)SEQ * HID, (long)SEQ * HID, NB, 0);

    // 5. qkv = x @ Wqkv + bqkv
    launch_gemm(x, Wqkv, bqkv, qkv, TOKENS, 3 * HID, HID, HID, 3 * HID, 3 * HID,
                0, 0, 0, 1, 0);

    // 6. fused flash attention — single launch, all segments
    flash_k<<<dim3(8, NB * NHEADS), 256, FLASH_SMEM_BYTES>>>(qkv, ctx, rowtab);

    // 7. x1 = LN1(x + ctx @ Wo + bo)
    gemm_ln<<<TOKENS / LBM, 256, LN_SMEM_BYTES>>>(ctx, Wo, bo, x, ln1g, ln1b,
                                                  x1, HID, HID);

    // 8. ff = relu(x1 @ w1p + b1p)
    launch_gemm(x1, w1p, b1p, ff, TOKENS, FFP, HID, HID, FFP, FFP, 0, 0, 0, 1, 1);

    // 9. x = LN2(x1 + ff @ w2p + bff2)
    gemm_ln<<<TOKENS / LBM, 256, LN_SMEM_BYTES>>>(ff, w2p, bff2, x1, ln2g, ln2b,
                                                  x, FFP, FFP);

    // 10. segment means (two-stage)
    zero_mean_k<<<NB * 3, 256>>>(mean);
    mean_part_k<<<dim3(NB * 3, 8), 256>>>(x, mean);

    // 11. out = relu((p - n + f) @ fc1W + fc1b)
    final_k<<<NB, 256>>>(mean, fc1W, fc1b, (float*)d_out);
}

// round 10
// speedup vs baseline: 1.8177x; 1.7434x over previous
#include <cuda_runtime.h>
#include <cuda_fp16.h>
#include <mma.h>

using namespace nvcuda;

// ---------------------------------------------------------------------------
// GraphEncoder: fp16 tensor-core GEMMs (fp32 accumulate) + fp16 flash attn.
// Shapes: B=16, S=1024 (segments 512/256/256), H=256, heads=4 (Dh=64), F=400.
// ---------------------------------------------------------------------------

#define NB 16
#define SEQ 1024
#define HID 256
#define NHEADS 4
#define DH 64
#define FFP 512
#define TOKENS (NB * SEQ)

// -------------------- scratch (device globals; no allocation) --------------
__device__ __half g_hth[NB * SEQ * SEQ];       // fp16 HT
__device__ __half g_h0h[TOKENS * HID];
__device__ __half g_th[TOKENS * HID];
__device__ __half g_xh[TOKENS * HID];
__device__ float  g_x32[TOKENS * HID];
__device__ __half g_x1h[TOKENS * HID];
__device__ float  g_x132[TOKENS * HID];
__device__ __half g_qkvh[TOKENS * 3 * HID];
__device__ __half g_ctxh[TOKENS * HID];
__device__ __half g_ffh[TOKENS * FFP];
__device__ float  g_xout[TOKENS * HID];
__device__ float  g_mean[NB * 3 * HID];
__device__ __half g_wg1h[HID * HID];
__device__ __half g_wg2h[HID * HID];
__device__ __half g_wqkvh[HID * 3 * HID];
__device__ __half g_woh[HID * HID];
__device__ __half g_w1ph[HID * FFP];
__device__ float  g_b1p[FFP];
__device__ __half g_w2ph[FFP * HID];
__device__ int    g_rowtab[256];
__device__ int    g_coltab[256];

__device__ __forceinline__ unsigned sptr(const void* p) {
    return (unsigned)__cvta_generic_to_shared(p);
}
#define CPA16(dst, src) asm volatile("cp.async.ca.shared.global [%0], [%1], 16;" :: "r"(dst), "l"(src))
#define CPA_COMMIT()    asm volatile("cp.async.commit_group;")
#define CPA_WAIT0()     asm volatile("cp.async.wait_group 0;")
#define CPA_WAIT1()     asm volatile("cp.async.wait_group 1;")

// FMA-pipe exp2 (no MUFU)
__device__ __forceinline__ float fexp2(float y) {
    y = fmaxf(y, -80.f);
    float t = y + 12582912.f;
    int   n = __float_as_int(t) - 0x4B400000;
    float f = y - (t - 12582912.f);
    float p = 1.f + f * (0.69314718f + f * (0.24022651f +
                   f * (0.05550411f + f * 0.00961813f)));
    return __int_as_float(__float_as_int(p) + (n << 23));
}
#define SM_SCALE 0.18033688f   // 0.125 * log2(e)

// -------------------- probe: fp32 acc (m16n16k16) element->(row,col) map ---
__global__ void probe_k(int* __restrict__ rowtab, int* __restrict__ coltab)
{
    __shared__ float pat[16 * 16];
    int lane = threadIdx.x;
    wmma::fragment<wmma::accumulator, 16, 16, 16, float> fr, fc;
    for (int i = lane; i < 256; i += 32) pat[i] = (float)(i >> 4);
    __syncwarp();
    wmma::load_matrix_sync(fr, pat, 16, wmma::mem_row_major);
    __syncwarp();
    for (int i = lane; i < 256; i += 32) pat[i] = (float)(i & 15);
    __syncwarp();
    wmma::load_matrix_sync(fc, pat, 16, wmma::mem_row_major);
#pragma unroll
    for (int e = 0; e < 8; e++) {
        rowtab[lane * 8 + e] = (int)fr.x[e];
        coltab[lane * 8 + e] = (int)fc.x[e];
    }
}

// -------------------- conversion / prep kernels ----------------------------
__global__ void cvt_k(const float* __restrict__ in, __half* __restrict__ out, int n)
{
    int i = blockIdx.x * 256 + threadIdx.x;
    if (i < n) out[i] = __float2half(in[i]);
}
__global__ void gather_h_k(const int* __restrict__ idx, const float* __restrict__ tab,
                           __half* __restrict__ out)
{
    long tok = blockIdx.x;
    int id = idx[tok];
    const float4 v = ((const float4*)(tab + (long)id * HID))[threadIdx.x];
    __half2* dst = (__half2*)(out + tok * HID) + threadIdx.x * 2;
    dst[0] = __floats2half2_rn(v.x, v.y);
    dst[1] = __floats2half2_rn(v.z, v.w);
}
__global__ void pad_w1_k(const float* __restrict__ w, __half* __restrict__ o)
{
    int i = blockIdx.x * 256 + threadIdx.x;
    int r = i >> 9, c = i & 511;
    o[i] = __float2half((c < 400) ? w[r * 400 + c] : 0.f);
}
__global__ void pad_b1_k(const float* __restrict__ b, float* __restrict__ o)
{
    int c = threadIdx.x + blockIdx.x * 256;
    o[c] = (c < 400) ? b[c] : 0.f;
}
__global__ void pad_w2_k(const float* __restrict__ w, __half* __restrict__ o)
{
    int i = blockIdx.x * 256 + threadIdx.x;
    int r = i >> 8, c = i & 255;
    o[i] = __float2half((r < 400) ? w[r * 256 + c] : 0.f);
}

// -------------------- fp16 GEMM (128x128 CTA, 128 thr, BK=32) --------------
// C = A@B + bias (relu?). M%128==0, N%128==0, K%32==0.
// Writes C16 always; C32 optionally (residual streams).
#define BKH 32
#define APH 40
#define BPH 136
#define ASH (128 * APH)                 // 5120 halfs
#define BSH (BKH * BPH)                 // 4352 halfs
#define STAGES 3
#define HBIAS_OFF (STAGES * (ASH + BSH))        // 28416 halfs (56832 B, 16B aligned)
#define GEMM_SMEM_BYTES (HBIAS_OFF * 2 + 16 * 132 * 4)

__global__ void __launch_bounds__(128, 2) gemm_h(
    const __half* __restrict__ A, const __half* __restrict__ Bm,
    const float* __restrict__ bias, __half* __restrict__ C16,
    float* __restrict__ C32,
    int K, int lda, int ldb, int ldc,
    long sAb, long sBb, long sCb, int relu,
    const int* __restrict__ rowtab, const int* __restrict__ coltab)
{
    extern __shared__ __half smh[];
    float* biasm = (float*)(smh + HBIAS_OFF);

    const int z = blockIdx.z;
    A  += (long)z * sAb;
    Bm += (long)z * sBb;

    const int tid = threadIdx.x;
    const int w = tid >> 5, lane = tid & 31;
    const int wm = w & 1, wn = w >> 1;          // 2x2 warps, 64x64
    const int rowTile = blockIdx.y * 128;
    const int colTile = blockIdx.x * 128;

    auto loadA = [&](int kt, int s) {
        const __half* Ag = A + (long)rowTile * lda + kt * BKH;
        __half* sa = smh + s * ASH;
#pragma unroll
        for (int i = 0; i < 4; i++) {
            int idx = tid + i * 128;            // 512 chunks: 128 rows x 4
            int r = idx >> 2, c8 = (idx & 3) * 8;
            CPA16(sptr(sa + r * APH + c8), Ag + (long)r * lda + c8);
        }
    };
    auto loadB = [&](int kt, int s) {
        const __half* Bg = Bm + (long)(kt * BKH) * ldb + colTile;
        __half* sb = smh + STAGES * ASH + s * BSH;
#pragma unroll
        for (int i = 0; i < 4; i++) {
            int idx = tid + i * 128;            // 512 chunks: 32 rows x 16
            int r = idx >> 4, c8 = (idx & 15) * 8;
            CPA16(sptr(sb + r * BPH + c8), Bg + (long)r * ldb + c8);
        }
    };

    if (bias) {
        for (int i = tid; i < 16 * 128; i += 128) {
            int r = i >> 7, c = i & 127;
            biasm[r * 132 + c] = bias[colTile + c];
        }
    }

    loadA(0, 0); loadB(0, 0); CPA_COMMIT();
    loadA(1, 1); loadB(1, 1); CPA_COMMIT();
    __syncthreads();

    wmma::fragment<wmma::accumulator, 16, 16, 16, float> acc[4][4];
    if (bias) {
#pragma unroll
        for (int ni = 0; ni < 4; ni++) {
            wmma::load_matrix_sync(acc[0][ni], biasm + wn * 64 + ni * 16, 132,
                                   wmma::mem_row_major);
#pragma unroll
            for (int mi = 1; mi < 4; mi++) acc[mi][ni] = acc[0][ni];
        }
    } else {
#pragma unroll
        for (int mi = 0; mi < 4; mi++)
#pragma unroll
            for (int ni = 0; ni < 4; ni++) wmma::fill_fragment(acc[mi][ni], 0.f);
    }

    const int nk = K / BKH;
    for (int kt = 0; kt < nk; kt++) {
        CPA_WAIT1();
        __syncthreads();
        if (kt + 2 < nk) { int s = (kt + 2) % STAGES; loadA(kt + 2, s); loadB(kt + 2, s); CPA_COMMIT(); }

        const __half* sa = smh + (kt % STAGES) * ASH;
        const __half* sb = smh + STAGES * ASH + (kt % STAGES) * BSH;

#pragma unroll
        for (int ks = 0; ks < 2; ks++) {
            wmma::fragment<wmma::matrix_a, 16, 16, 16, __half, wmma::row_major> af[4];
#pragma unroll
            for (int mi = 0; mi < 4; mi++)
                wmma::load_matrix_sync(af[mi], sa + (wm * 64 + mi * 16) * APH + ks * 16, APH);
            wmma::fragment<wmma::matrix_b, 16, 16, 16, __half, wmma::row_major> bf[4];
#pragma unroll
            for (int ni = 0; ni < 4; ni++)
                wmma::load_matrix_sync(bf[ni], sb + (ks * 16) * BPH + wn * 64 + ni * 16, BPH);
#pragma unroll
            for (int mi = 0; mi < 4; mi++)
#pragma unroll
                for (int ni = 0; ni < 4; ni++)
                    wmma::mma_sync(acc[mi][ni], af[mi], bf[ni], acc[mi][ni]);
        }
    }

    // direct epilogue via probed (row,col) maps
    int rt[8], ct[8];
#pragma unroll
    for (int e = 0; e < 8; e++) { rt[e] = rowtab[lane * 8 + e]; ct[e] = coltab[lane * 8 + e]; }

    __half* C16z = C16 + (long)z * sCb;
    float*  C32z = C32 ? C32 + (long)z * sCb : nullptr;
#pragma unroll
    for (int mi = 0; mi < 4; mi++)
#pragma unroll
        for (int ni = 0; ni < 4; ni++) {
            long rbase = (long)(rowTile + wm * 64 + mi * 16);
            int  cbase = colTile + wn * 64 + ni * 16;
#pragma unroll
            for (int e = 0; e < 8; e++) {
                float v = acc[mi][ni].x[e];
                if (relu) v = fmaxf(v, 0.f);
                long off = (rbase + rt[e]) * ldc + cbase + ct[e];
                C16z[off] = __float2half(v);
                if (C32z) C32z[off] = v;
            }
        }
}

// -------------------- fp16 GEMM + residual + LayerNorm ---------------------
// out32 = LN(res + A@B + bias); out16 optional. N == 256.
#define LAPH 40
#define LBPH 264
#define LASH (128 * LAPH)               // 5120 halfs
#define LBSH (BKH * LBPH)               // 8448 halfs
#define LEPI_OFF (STAGES * (LASH + LBSH))     // 40704 halfs (81408 B)
#define LBPADF 260
#define LN_SMEM_BYTES (LEPI_OFF * 2 + (128 * LBPADF + 2 * 128) * 4)

__global__ void __launch_bounds__(256, 1) gemm_ln_h(
    const __half* __restrict__ A, const __half* __restrict__ Bm,
    const float* __restrict__ bias, const float* __restrict__ res,
    const float* __restrict__ lng, const float* __restrict__ lnb,
    float* __restrict__ out32, __half* __restrict__ out16,
    int K, int lda)
{
    extern __shared__ __half smh[];
    float* epi = (float*)(smh + LEPI_OFF);
    float* smu = epi + 128 * LBPADF;
    float* srs = smu + 128;

    const int tid = threadIdx.x;
    const int w = tid >> 5;
    const int wm = w & 1, wn = w >> 1;          // 2x4 warps, 64x64
    const int rowTile = blockIdx.x * 128;

    auto loadA = [&](int kt, int s) {
        const __half* Ag = A + (long)rowTile * lda + kt * BKH;
        __half* sa = smh + s * LASH;
#pragma unroll
        for (int i = 0; i < 2; i++) {
            int idx = tid + i * 256;
            int r = idx >> 2, c8 = (idx & 3) * 8;
            CPA16(sptr(sa + r * LAPH + c8), Ag + (long)r * lda + c8);
        }
    };
    auto loadB = [&](int kt, int s) {
        const __half* Bg = Bm + (long)(kt * BKH) * 256;
        __half* sb = smh + STAGES * LASH + s * LBSH;
#pragma unroll
        for (int i = 0; i < 4; i++) {
            int idx = tid + i * 256;            // 1024 chunks: 32 rows x 32
            int r = idx >> 5, c8 = (idx & 31) * 8;
            CPA16(sptr(sb + r * LBPH + c8), Bg + (long)r * 256 + c8);
        }
    };

    loadA(0, 0); loadB(0, 0); CPA_COMMIT();
    loadA(1, 1); loadB(1, 1); CPA_COMMIT();

    wmma::fragment<wmma::accumulator, 16, 16, 16, float> acc[4][4];
#pragma unroll
    for (int mi = 0; mi < 4; mi++)
#pragma unroll
        for (int ni = 0; ni < 4; ni++) wmma::fill_fragment(acc[mi][ni], 0.f);

    const int nk = K / BKH;
    for (int kt = 0; kt < nk; kt++) {
        CPA_WAIT1();
        __syncthreads();
        if (kt + 2 < nk) { int s = (kt + 2) % STAGES; loadA(kt + 2, s); loadB(kt + 2, s); CPA_COMMIT(); }

        const __half* sa = smh + (kt % STAGES) * LASH;
        const __half* sb = smh + STAGES * LASH + (kt % STAGES) * LBSH;

#pragma unroll
        for (int ks = 0; ks < 2; ks++) {
            wmma::fragment<wmma::matrix_a, 16, 16, 16, __half, wmma::row_major> af[4];
#pragma unroll
            for (int mi = 0; mi < 4; mi++)
                wmma::load_matrix_sync(af[mi], sa + (wm * 64 + mi * 16) * LAPH + ks * 16, LAPH);
            wmma::fragment<wmma::matrix_b, 16, 16, 16, __half, wmma::row_major> bf[4];
#pragma unroll
            for (int ni = 0; ni < 4; ni++)
                wmma::load_matrix_sync(bf[ni], sb + (ks * 16) * LBPH + wn * 64 + ni * 16, LBPH);
#pragma unroll
            for (int mi = 0; mi < 4; mi++)
#pragma unroll
                for (int ni = 0; ni < 4; ni++)
                    wmma::mma_sync(acc[mi][ni], af[mi], bf[ni], acc[mi][ni]);
        }
    }
    __syncthreads();

#pragma unroll
    for (int mi = 0; mi < 4; mi++)
#pragma unroll
        for (int ni = 0; ni < 4; ni++)
            wmma::store_matrix_sync(epi + (wm * 64 + mi * 16) * LBPADF + wn * 64 + ni * 16,
                                    acc[mi][ni], LBPADF, wmma::mem_row_major);
    __syncthreads();

#pragma unroll 8
    for (int i = 0; i < 128; i++) {
        int idx = tid + i * 256;
        int r = idx >> 8, c = idx & 255;
        epi[r * LBPADF + c] += bias[c] + res[(long)(rowTile + r) * HID + c];
    }
    __syncthreads();

    {
        const int r = tid >> 1, hf = tid & 1;
        const float* row = epi + r * LBPADF + hf * 128;
        float s = 0.f, s2 = 0.f;
#pragma unroll 8
        for (int c = 0; c < 128; c++) { float v = row[c]; s += v; s2 += v * v; }
        s  += __shfl_xor_sync(0xffffffffu, s, 1);
        s2 += __shfl_xor_sync(0xffffffffu, s2, 1);
        if (hf == 0) {
            float mu = s * (1.f / 256.f);
            float var = s2 * (1.f / 256.f) - mu * mu;
            smu[r] = mu;
            srs[r] = rsqrtf(var + 1e-5f);
        }
    }
    __syncthreads();

#pragma unroll 8
    for (int i = 0; i < 128; i++) {
        int idx = tid + i * 256;
        int r = idx >> 8, c = idx & 255;
        float v = (epi[r * LBPADF + c] - smu[r]) * srs[r] * lng[c] + lnb[c];
        long off = (long)(rowTile + r) * HID + c;
        out32[off] = v;
        if (out16) out16[off] = __float2half(v);
    }
}

// -------------------- fp16 flash attention ---------------------------------
#define QLDH 72
#define SLDF 132
#define PLDH 136
// half offsets
#define FS_Q 0
#define FS_K (128 * QLDH)               // 9216
#define FS_V (2 * 128 * QLDH)           // 18432
#define FS_P (3 * 128 * QLDH)           // 27648 .. +128*136=17408 -> 45056
// float region after halfs: place at half offset 45056 (byte 90112, 16B aligned)
#define FS_F 45056
#define FLASH_SMEM_BYTES (FS_F * 2 + (128 * SLDF + 3 * 128) * 4)

__global__ void __launch_bounds__(256) flash_k(
    const __half* __restrict__ qkv, __half* __restrict__ ctx,
    const int* __restrict__ rowtab, const int* __restrict__ coltab)
{
    extern __shared__ __half smh[];
    __half* sQ = smh + FS_Q;
    __half* sK = smh + FS_K;
    __half* sV = smh + FS_V;
    __half* sP = smh + FS_P;
    float* sS = (float*)(smh + FS_F);
    float* al = sS + 128 * SLDF;
    float* mrow = al + 128;
    float* lrow = mrow + 128;

    const int bx = blockIdx.x;
    int segOff, L, qt;
    if (bx < 4)      { segOff = 0;   L = 512; qt = bx; }
    else if (bx < 6) { segOff = 512; L = 256; qt = bx - 4; }
    else             { segOff = 768; L = 256; qt = bx - 6; }

    const int bh = blockIdx.y;
    const int b = bh >> 2, h = bh & 3;
    const int tid = threadIdx.x;
    const int w = tid >> 5, lane = tid & 31;
    const int wm = w & 3, wn = w >> 2;

    const __half* base = qkv + ((long)b * SEQ + segOff) * 768 + h * 64;

    auto loadT = [&](const __half* g, __half* s) {
#pragma unroll
        for (int i = 0; i < 4; i++) {
            int idx = tid + i * 256;            // 1024 chunks: 128 rows x 8
            int r = idx >> 3, c8 = (idx & 7) * 8;
            CPA16(sptr(s + r * QLDH + c8), g + (long)r * 768 + c8);
        }
    };

    int rt[8], ctb[8];
#pragma unroll
    for (int e = 0; e < 8; e++) { rt[e] = rowtab[lane * 8 + e]; ctb[e] = coltab[lane * 8 + e]; }

    if (tid < 128) { mrow[tid] = -1e30f; lrow[tid] = 0.f; }

    loadT(base + (long)qt * 128 * 768, sQ);
    loadT(base + 256, sK); CPA_COMMIT();
    loadT(base + 512, sV); CPA_COMMIT();

    wmma::fragment<wmma::accumulator, 16, 16, 16, float> oacc[2][2];
#pragma unroll
    for (int mi = 0; mi < 2; mi++)
#pragma unroll
        for (int ni = 0; ni < 2; ni++) wmma::fill_fragment(oacc[mi][ni], 0.f);

    const int nt = L >> 7;
    for (int t = 0; t < nt; t++) {
        CPA_WAIT1();
        __syncthreads();

        // ---- S = Q @ K^T ----
        {
            wmma::fragment<wmma::accumulator, 16, 16, 16, float> sacc[2][4];
#pragma unroll
            for (int mi = 0; mi < 2; mi++)
#pragma unroll
                for (int ni = 0; ni < 4; ni++) wmma::fill_fragment(sacc[mi][ni], 0.f);
#pragma unroll
            for (int k = 0; k < DH; k += 16) {
                wmma::fragment<wmma::matrix_a, 16, 16, 16, __half, wmma::row_major> af[2];
#pragma unroll
                for (int mi = 0; mi < 2; mi++)
                    wmma::load_matrix_sync(af[mi], sQ + (wm * 32 + mi * 16) * QLDH + k, QLDH);
                wmma::fragment<wmma::matrix_b, 16, 16, 16, __half, wmma::col_major> bf[4];
#pragma unroll
                for (int ni = 0; ni < 4; ni++)
                    wmma::load_matrix_sync(bf[ni], sK + (wn * 64 + ni * 16) * QLDH + k, QLDH);
#pragma unroll
                for (int mi = 0; mi < 2; mi++)
#pragma unroll
                    for (int ni = 0; ni < 4; ni++)
                        wmma::mma_sync(sacc[mi][ni], af[mi], bf[ni], sacc[mi][ni]);
            }
#pragma unroll
            for (int mi = 0; mi < 2; mi++)
#pragma unroll
                for (int ni = 0; ni < 4; ni++)
                    wmma::store_matrix_sync(sS + (wm * 32 + mi * 16) * SLDF + wn * 64 + ni * 16,
                                            sacc[mi][ni], SLDF, wmma::mem_row_major);
        }
        __syncthreads();

        if (t + 1 < nt) { loadT(base + 256 + (long)(t + 1) * 128 * 768, sK); CPA_COMMIT(); }

        // ---- online softmax (fp32), P -> fp16 ----
        {
            const int r = tid >> 1, hf = tid & 1;
            float* row = sS + r * SLDF + hf * 64;
            __half* prow = sP + r * PLDH + hf * 64;
            float mx = -1e30f;
#pragma unroll 8
            for (int c = 0; c < 64; c++) mx = fmaxf(mx, row[c]);
            mx = fmaxf(mx, __shfl_xor_sync(0xffffffffu, mx, 1));
            mx *= SM_SCALE;
            float m_old = mrow[r];
            float m_new = fmaxf(m_old, mx);
            float a = fexp2(m_old - m_new);
            float sum = 0.f;
#pragma unroll 4
            for (int c = 0; c < 64; c++) {
                float p = fexp2(row[c] * SM_SCALE - m_new);
                prow[c] = __float2half(p);
                sum += p;
            }
            sum += __shfl_xor_sync(0xffffffffu, sum, 1);
            if (hf == 0) {
                mrow[r] = m_new;
                lrow[r] = lrow[r] * a + sum;
                al[r] = a;
            }
        }
        if (t + 1 < nt) { CPA_WAIT1(); } else { CPA_WAIT0(); }
        __syncthreads();

        // ---- rescale O (registers), accumulate P @ V ----
        {
            float av[2][8];
#pragma unroll
            for (int mi = 0; mi < 2; mi++)
#pragma unroll
                for (int e = 0; e < 8; e++)
                    av[mi][e] = al[wm * 32 + mi * 16 + rt[e]];
#pragma unroll
            for (int mi = 0; mi < 2; mi++)
#pragma unroll
                for (int ni = 0; ni < 2; ni++)
#pragma unroll
                    for (int e = 0; e < 8; e++)
                        oacc[mi][ni].x[e] *= av[mi][e];

#pragma unroll
            for (int k = 0; k < 128; k += 16) {
                wmma::fragment<wmma::matrix_a, 16, 16, 16, __half, wmma::row_major> af[2];
#pragma unroll
                for (int mi = 0; mi < 2; mi++)
                    wmma::load_matrix_sync(af[mi], sP + (wm * 32 + mi * 16) * PLDH + k, PLDH);
                wmma::fragment<wmma::matrix_b, 16, 16, 16, __half, wmma::row_major> bf[2];
#pragma unroll
                for (int ni = 0; ni < 2; ni++)
                    wmma::load_matrix_sync(bf[ni], sV + k * QLDH + wn * 32 + ni * 16, QLDH);
#pragma unroll
                for (int mi = 0; mi < 2; mi++)
#pragma unroll
                    for (int ni = 0; ni < 2; ni++)
                        wmma::mma_sync(oacc[mi][ni], af[mi], bf[ni], oacc[mi][ni]);
            }
        }
        __syncthreads();
        if (t + 1 < nt) { loadT(base + 512 + (long)(t + 1) * 128 * 768, sV); CPA_COMMIT(); }
    }

    if (tid < 128) al[tid] = 1.f / lrow[tid];
    __syncthreads();
    {
        __half* outp = ctx + ((long)b * SEQ + segOff + (long)qt * 128) * HID + h * 64;
#pragma unroll
        for (int mi = 0; mi < 2; mi++) {
            float iv[8];
#pragma unroll
            for (int e = 0; e < 8; e++) iv[e] = al[wm * 32 + mi * 16 + rt[e]];
#pragma unroll
            for (int ni = 0; ni < 2; ni++) {
                long rbase = (long)(wm * 32 + mi * 16);
                int  cbase = wn * 32 + ni * 16;
#pragma unroll
                for (int e = 0; e < 8; e++)
                    outp[(rbase + rt[e]) * HID + cbase + ctb[e]] =
                        __float2half(oacc[mi][ni].x[e] * iv[e]);
            }
        }
    }
}

// -------------------- small kernels -----------------------------------------
__global__ void zero_mean_k(float* __restrict__ m)
{
    m[blockIdx.x * 256 + threadIdx.x] = 0.f;
}
__global__ void mean_part_k(const float* __restrict__ x, float* __restrict__ mout)
{
    int seg = blockIdx.x, part = blockIdx.y;
    int b = seg / 3, sgi = seg % 3;
    int off = (sgi == 0) ? 0 : (sgi == 1 ? 512 : 768);
    int L   = (sgi == 0) ? 512 : 256;
    int rows = L >> 3;
    int t = threadIdx.x;
    const float* p = x + ((long)b * SEQ + off + part * rows) * HID + t;
    float s = 0.f;
    for (int i = 0; i < rows; i++) s += p[(long)i * HID];
    atomicAdd(&mout[(long)seg * HID + t], s);
}
__global__ void final_k(const float* __restrict__ mean, const float* __restrict__ W,
                        const float* __restrict__ bias, float* __restrict__ out)
{
    int b = blockIdx.x, n = threadIdx.x;
    __shared__ float comb[HID];
    const float* mp = mean + (long)b * 3 * HID;
    comb[n] = mp[n] * (1.f / 512.f) - mp[HID + n] * (1.f / 256.f)
            + mp[2 * HID + n] * (1.f / 256.f);
    __syncthreads();
    float s = bias[n];
#pragma unroll 8
    for (int k = 0; k < HID; k++) s += comb[k] * W[k * HID + n];
    out[(long)b * HID + n] = fmaxf(s, 0.f);
}

// ---------------------------------------------------------------------------
static void launch_gemm(const __half* A, const __half* B, const float* bias,
                        __half* C16, float* C32,
                        int M, int N, int K, int lda, int ldb, int ldc,
                        long sAb, long sBb, long sCb, int batches, int relu,
                        const int* rowtab, const int* coltab)
{
    dim3 grid(N / 128, M / 128, batches);
    gemm_h<<<grid, 128, GEMM_SMEM_BYTES>>>(A, B, bias, C16, C32, K, lda, ldb, ldc,
                                           sAb, sBb, sCb, relu, rowtab, coltab);
}

extern "C" void kernel_launch(void* const* d_in, const int* in_sizes, int n_in,
                              void* d_out, int out_size)
{
    const int*   hyper = (const int*)  d_in[0];
    const float* HT    = (const float*)d_in[1];
    const float* emb   = (const float*)d_in[2];
    const float* Wg1   = (const float*)d_in[3];
    const float* bg1   = (const float*)d_in[4];
    const float* Wg2   = (const float*)d_in[5];
    const float* bg2   = (const float*)d_in[6];
    const float* Wqkv  = (const float*)d_in[7];
    const float* bqkv  = (const float*)d_in[8];
    const float* Wo    = (const float*)d_in[9];
    const float* bo    = (const float*)d_in[10];
    const float* ln1g  = (const float*)d_in[11];
    const float* ln1b  = (const float*)d_in[12];
    const float* Wff1  = (const float*)d_in[13];
    const float* bff1  = (const float*)d_in[14];
    const float* Wff2  = (const float*)d_in[15];
    const float* bff2  = (const float*)d_in[16];
    const float* ln2g  = (const float*)d_in[17];
    const float* ln2b  = (const float*)d_in[18];
    const float* fc1W  = (const float*)d_in[19];
    const float* fc1b  = (const float*)d_in[20];

    __half *hth, *h0h, *th, *xh, *x1h, *qkvh, *ctxh, *ffh;
    __half *wg1h, *wg2h, *wqkvh, *woh, *w1ph, *w2ph;
    float *x32, *x132, *xout, *mean, *b1p;
    int *rowtab, *coltab;
    cudaGetSymbolAddress((void**)&hth,   g_hth);
    cudaGetSymbolAddress((void**)&h0h,   g_h0h);
    cudaGetSymbolAddress((void**)&th,    g_th);
    cudaGetSymbolAddress((void**)&xh,    g_xh);
    cudaGetSymbolAddress((void**)&x32,   g_x32);
    cudaGetSymbolAddress((void**)&x1h,   g_x1h);
    cudaGetSymbolAddress((void**)&x132,  g_x132);
    cudaGetSymbolAddress((void**)&qkvh,  g_qkvh);
    cudaGetSymbolAddress((void**)&ctxh,  g_ctxh);
    cudaGetSymbolAddress((void**)&ffh,   g_ffh);
    cudaGetSymbolAddress((void**)&xout,  g_xout);
    cudaGetSymbolAddress((void**)&mean,  g_mean);
    cudaGetSymbolAddress((void**)&wg1h,  g_wg1h);
    cudaGetSymbolAddress((void**)&wg2h,  g_wg2h);
    cudaGetSymbolAddress((void**)&wqkvh, g_wqkvh);
    cudaGetSymbolAddress((void**)&woh,   g_woh);
    cudaGetSymbolAddress((void**)&w1ph,  g_w1ph);
    cudaGetSymbolAddress((void**)&b1p,   g_b1p);
    cudaGetSymbolAddress((void**)&w2ph,  g_w2ph);
    cudaGetSymbolAddress((void**)&rowtab, g_rowtab);
    cudaGetSymbolAddress((void**)&coltab, g_coltab);

    cudaFuncSetAttribute(flash_k, cudaFuncAttributeMaxDynamicSharedMemorySize,
                         FLASH_SMEM_BYTES);
    cudaFuncSetAttribute(gemm_h, cudaFuncAttributeMaxDynamicSharedMemorySize,
                         GEMM_SMEM_BYTES);
    cudaFuncSetAttribute(gemm_ln_h, cudaFuncAttributeMaxDynamicSharedMemorySize,
                         LN_SMEM_BYTES);

    // 0. probe + conversions
    probe_k<<<1, 32>>>(rowtab, coltab);
    cvt_k<<<(NB * SEQ * SEQ + 255) / 256, 256>>>(HT, hth, NB * SEQ * SEQ);
    gather_h_k<<<TOKENS, 64>>>(hyper, emb, h0h);
    cvt_k<<<(HID * HID + 255) / 256, 256>>>(Wg1, wg1h, HID * HID);
    cvt_k<<<(HID * HID + 255) / 256, 256>>>(Wg2, wg2h, HID * HID);
    cvt_k<<<(HID * 3 * HID + 255) / 256, 256>>>(Wqkv, wqkvh, HID * 3 * HID);
    cvt_k<<<(HID * HID + 255) / 256, 256>>>(Wo, woh, HID * HID);
    pad_w1_k<<<HID * FFP / 256, 256>>>(Wff1, w1ph);
    pad_b1_k<<<2, 256>>>(bff1, b1p);
    pad_w2_k<<<FFP * HID / 256, 256>>>(Wff2, w2ph);

    // 1. t = h0 @ Wg1
    launch_gemm(h0h, wg1h, nullptr, th, nullptr, TOKENS, HID, HID, HID, HID, HID,
                0, 0, 0, 1, 0, rowtab, coltab);

    // 2. x = batched HT @ t + bg1   (fp16 out only)
    launch_gemm(hth, th, bg1, xh, nullptr, SEQ, HID, SEQ, SEQ, HID, HID,
                (long)SEQ * SEQ, (long)SEQ * HID, (long)SEQ * HID, NB, 0,
                rowtab, coltab);

    // 3. t = x @ Wg2
    launch_gemm(xh, wg2h, nullptr, th, nullptr, TOKENS, HID, HID, HID, HID, HID,
                0, 0, 0, 1, 0, rowtab, coltab);

    // 4. x = batched HT @ t + bg2   (fp16 + fp32 for LN1 residual)
    launch_gemm(hth, th, bg2, xh, x32, SEQ, HID, SEQ, SEQ, HID, HID,
                (long)SEQ * SEQ, (long)SEQ * HID, (long)SEQ * HID, NB, 0,
                rowtab, coltab);

    // 5. qkv = x @ Wqkv + bqkv
    launch_gemm(xh, wqkvh, bqkv, qkvh, nullptr, TOKENS, 3 * HID, HID,
                HID, 3 * HID, 3 * HID, 0, 0, 0, 1, 0, rowtab, coltab);

    // 6. flash attention (single launch)
    flash_k<<<dim3(8, NB * NHEADS), 256, FLASH_SMEM_BYTES>>>(qkvh, ctxh, rowtab, coltab);

    // 7. x1 = LN1(x + ctx @ Wo + bo)   (fp32 + fp16)
    gemm_ln_h<<<TOKENS / 128, 256, LN_SMEM_BYTES>>>(ctxh, woh, bo, x32,
                                                    ln1g, ln1b, x132, x1h, HID, HID);

    // 8. ff = relu(x1 @ w1p + b1p)
    launch_gemm(x1h, w1ph, b1p, ffh, nullptr, TOKENS, FFP, HID, HID, FFP, FFP,
                0, 0, 0, 1, 1, rowtab, coltab);

    // 9. x = LN2(x1 + ff @ w2p + bff2)   (fp32 only; feeds mean)
    gemm_ln_h<<<TOKENS / 128, 256, LN_SMEM_BYTES>>>(ffh, w2ph, bff2, x132,
                                                    ln2g, ln2b, xout, nullptr, FFP, FFP);

    // 10. segment means (two-stage)
    zero_mean_k<<<NB * 3, 256>>>(mean);
    mean_part_k<<<dim3(NB * 3, 8), 256>>>(xout, mean);

    // 11. out = relu((p - n + f) @ fc1W + fc1b)
    final_k<<<NB, 256>>>(mean, fc1W, fc1b, (float*)d_out);
}